// round 6
// baseline (speedup 1.0000x reference)
#include <cuda_runtime.h>
#include <cuda_fp16.h>
#include <math.h>
#include <stdint.h>

#define Bx  16
#define Sx  512
#define Vx  512
#define Hx  1024
#define NLx 8
#define NHx 16
#define DHx 64
#define Fx  4096
#define Mx  (Bx*Sx)

#define LOG2E 1.4426950408889634f

// ---------------- scratch ----------------
__device__ float g_x[Mx*Hx];
__device__ float g_h[Mx*Hx];
__device__ float g_qkv[Mx*3*Hx];
__device__ float g_attn[Mx*Hx];
__device__ float g_mid[(size_t)Mx*Fx];

// ---------------- helpers ----------------
__device__ __forceinline__ float to_tf32(float x) {
    float r;
    asm("cvt.rna.tf32.f32 %0, %1;" : "=f"(r) : "f"(x));
    return r;
}
__device__ __forceinline__ float ex2(float x) {
    float r;
    asm("ex2.approx.f32 %0, %1;" : "=f"(r) : "f"(x));
    return r;
}
__device__ __forceinline__ void mma_tf32(float* c, const uint32_t* a, const uint32_t* b) {
    asm volatile(
        "mma.sync.aligned.m16n8k8.row.col.f32.tf32.tf32.f32 "
        "{%0,%1,%2,%3}, {%4,%5,%6,%7}, {%8,%9}, {%0,%1,%2,%3};\n"
        : "+f"(c[0]), "+f"(c[1]), "+f"(c[2]), "+f"(c[3])
        : "r"(a[0]), "r"(a[1]), "r"(a[2]), "r"(a[3]), "r"(b[0]), "r"(b[1]));
}
__device__ __forceinline__ void mma_f16(float* c, const uint32_t* a, const uint32_t* b) {
    asm volatile(
        "mma.sync.aligned.m16n8k16.row.col.f32.f16.f16.f32 "
        "{%0,%1,%2,%3}, {%4,%5,%6,%7}, {%8,%9}, {%0,%1,%2,%3};\n"
        : "+f"(c[0]), "+f"(c[1]), "+f"(c[2]), "+f"(c[3])
        : "r"(a[0]), "r"(a[1]), "r"(a[2]), "r"(a[3]), "r"(b[0]), "r"(b[1]));
}
__device__ __forceinline__ float gelu_f(float v) {
    return 0.5f * v * (1.0f + tanhf(0.7978845608028654f * (v + 0.044715f * v * v * v)));
}

// ---------------- embedding ----------------
__global__ __launch_bounds__(256) void embed_kernel(const int* __restrict__ ids,
                                                    const float* __restrict__ emb,
                                                    float* __restrict__ out) {
    int m = blockIdx.x, t = threadIdx.x;
    int id = ids[m];
    ((float4*)(out + (size_t)m * Hx))[t] = ((const float4*)(emb + (size_t)id * Hx))[t];
}

// ---------------- layernorm ----------------
__global__ __launch_bounds__(256) void ln_kernel(const float* __restrict__ x,
                                                 const float* __restrict__ g,
                                                 const float* __restrict__ b,
                                                 float* __restrict__ out) {
    int m = blockIdx.x, t = threadIdx.x;
    __shared__ float red[8];
    float4 v = ((const float4*)(x + (size_t)m * Hx))[t];

    float s = v.x + v.y + v.z + v.w;
#pragma unroll
    for (int o = 16; o; o >>= 1) s += __shfl_xor_sync(0xffffffffu, s, o);
    if ((t & 31) == 0) red[t >> 5] = s;
    __syncthreads();
    float mu = 0.f;
#pragma unroll
    for (int w = 0; w < 8; w++) mu += red[w];
    mu *= (1.0f / Hx);
    __syncthreads();

    float d0 = v.x - mu, d1 = v.y - mu, d2 = v.z - mu, d3 = v.w - mu;
    float s2 = d0*d0 + d1*d1 + d2*d2 + d3*d3;
#pragma unroll
    for (int o = 16; o; o >>= 1) s2 += __shfl_xor_sync(0xffffffffu, s2, o);
    if ((t & 31) == 0) red[t >> 5] = s2;
    __syncthreads();
    float var = 0.f;
#pragma unroll
    for (int w = 0; w < 8; w++) var += red[w];
    var *= (1.0f / Hx);
    float inv = rsqrtf(var + 1e-5f);

    float4 gg = ((const float4*)g)[t];
    float4 bb = ((const float4*)b)[t];
    float4 o4;
    o4.x = d0 * inv * gg.x + bb.x;
    o4.y = d1 * inv * gg.y + bb.y;
    o4.z = d2 * inv * gg.z + bb.z;
    o4.w = d3 * inv * gg.w + bb.w;
    ((float4*)(out + (size_t)m * Hx))[t] = o4;
}

// ======= fp16 tensor-core GEMM: C = f(A@W + bias) (+resid) ==================
// CTA tile 128x128, K-step 32. A[m][k] half smem stride 40; B = W^T [n][k]
// half smem stride 40. m16n8k16 f16 mma, fp32 accum. 8 warps, 32x64 warp tile.
#define HST 40   // half stride: frag banks (20g+q) mod 32 all distinct

template<bool GELU, bool RESID>
__global__ __launch_bounds__(256) void gemm_h(const float* __restrict__ A,
                                              const float* __restrict__ W,
                                              const float* __restrict__ bias,
                                              const float* __restrict__ R,
                                              float* __restrict__ C,
                                              int M, int N, int K) {
    __shared__ half As[128 * HST];
    __shared__ half Bs[128 * HST];

    const int t = threadIdx.x;
    const int warp = t >> 5, lane = t & 31;
    const int g = lane >> 2, q = lane & 3;
    const int wm = warp >> 1;
    const int wn = warp & 1;
    const int m0 = blockIdx.y * 128, n0 = blockIdx.x * 128;

    const int a_rb = t >> 3, a_c4 = (t & 7) * 4;
    const int b_nn = t & 127, b_kg = t >> 7;

    float acc[2][8][4];
#pragma unroll
    for (int mt = 0; mt < 2; mt++)
#pragma unroll
        for (int nt = 0; nt < 8; nt++)
#pragma unroll
            for (int r = 0; r < 4; r++) acc[mt][nt][r] = 0.f;

    for (int k0 = 0; k0 < K; k0 += 32) {
        // ---- A tile: 128 rows x 32 k -> half
#pragma unroll
        for (int p = 0; p < 4; p++) {
            int row = a_rb + p * 32;
            float4 a = *(const float4*)(A + (size_t)(m0 + row) * K + k0 + a_c4);
            half2 h0 = __floats2half2_rn(a.x, a.y);
            half2 h1 = __floats2half2_rn(a.z, a.w);
            *(half2*)&As[row * HST + a_c4] = h0;
            *(half2*)&As[row * HST + a_c4 + 2] = h1;
        }
        // ---- B tile: W[k][n] -> Bs[n][k] transposed
#pragma unroll
        for (int p = 0; p < 16; p++) {
            int kk = b_kg + p * 2;
            Bs[b_nn * HST + kk] = __float2half_rn(W[(size_t)(k0 + kk) * N + n0 + b_nn]);
        }
        __syncthreads();

#pragma unroll
        for (int ks = 0; ks < 2; ks++) {
            const int k = ks * 16;
            uint32_t af[2][4], bf[8][2];
#pragma unroll
            for (int mt = 0; mt < 2; mt++) {
                int r = wm * 32 + mt * 16 + g;
                af[mt][0] = *(const uint32_t*)&As[(r    ) * HST + k + 2 * q];
                af[mt][1] = *(const uint32_t*)&As[(r + 8) * HST + k + 2 * q];
                af[mt][2] = *(const uint32_t*)&As[(r    ) * HST + k + 2 * q + 8];
                af[mt][3] = *(const uint32_t*)&As[(r + 8) * HST + k + 2 * q + 8];
            }
#pragma unroll
            for (int nt = 0; nt < 8; nt++) {
                int n = wn * 64 + nt * 8 + g;
                bf[nt][0] = *(const uint32_t*)&Bs[n * HST + k + 2 * q];
                bf[nt][1] = *(const uint32_t*)&Bs[n * HST + k + 2 * q + 8];
            }
#pragma unroll
            for (int mt = 0; mt < 2; mt++)
#pragma unroll
                for (int nt = 0; nt < 8; nt++)
                    mma_f16(acc[mt][nt], af[mt], bf[nt]);
        }
        __syncthreads();
    }

    // ---- epilogue
#pragma unroll
    for (int mt = 0; mt < 2; mt++) {
#pragma unroll
        for (int nt = 0; nt < 8; nt++) {
            int r0 = m0 + wm * 32 + mt * 16 + g;
            int c0 = n0 + wn * 64 + nt * 8 + q * 2;
            float b0 = bias ? bias[c0] : 0.f;
            float b1 = bias ? bias[c0 + 1] : 0.f;
#pragma unroll
            for (int half_i = 0; half_i < 2; half_i++) {
                int row = r0 + half_i * 8;
                float v0 = acc[mt][nt][half_i * 2 + 0] + b0;
                float v1 = acc[mt][nt][half_i * 2 + 1] + b1;
                if (GELU) { v0 = gelu_f(v0); v1 = gelu_f(v1); }
                if (RESID) {
                    const float2 rr = *(const float2*)(R + (size_t)row * N + c0);
                    v0 += rr.x; v1 += rr.y;
                }
                float2 o2; o2.x = v0; o2.y = v1;
                *(float2*)(C + (size_t)row * N + c0) = o2;
            }
        }
    }
}

// ---------------- fused flash attention (tf32 mma, online softmax) ----------
#define ATTN_SMEM_FLOATS (64*68*3 + 64*72)

__global__ __launch_bounds__(128) void attn_kernel(const float* __restrict__ qkv,
                                                   const int* __restrict__ sp,
                                                   float* __restrict__ attn) {
    extern __shared__ float sm[];
    float* Qs = sm;
    float* Ks = Qs + 64 * 68;
    float* Vs = Ks + 64 * 68;
    float* Ps = Vs + 64 * 72;

    const int it = blockIdx.x, bn = blockIdx.y;
    const int b = bn >> 4, n = bn & 15;
    const int t = threadIdx.x, w = t >> 5, lane = t & 31;
    const int g = lane >> 2, q = lane & 3;
    const int i0 = it * 64;
    const int spv = sp[b];
    const float slope2 = exp2f(-0.5f * (float)(n + 1)) * LOG2E;
    const float qscale = 0.125f * LOG2E;

#pragma unroll
    for (int l = 0; l < 8; l++) {
        int e = t + l * 128;
        int row = e >> 4, d4 = (e & 15) * 4;
        float4 v = *(const float4*)(qkv + (size_t)(b * Sx + i0 + row) * 3072 + n * 64 + d4);
        v.x = to_tf32(v.x * qscale); v.y = to_tf32(v.y * qscale);
        v.z = to_tf32(v.z * qscale); v.w = to_tf32(v.w * qscale);
        *(float4*)&Qs[row * 68 + d4] = v;
    }

    float o[8][4];
#pragma unroll
    for (int nt = 0; nt < 8; nt++)
#pragma unroll
        for (int c = 0; c < 4; c++) o[nt][c] = 0.f;
    float m0 = -1e30f, m1 = -1e30f, l0 = 0.f, l1 = 0.f;

    const int r0 = w * 16 + g;
    const int rowA = i0 + r0, rowB = rowA + 8;

    for (int jt = 0; jt <= it; jt++) {
        const int j0 = jt * 64;
        __syncthreads();
#pragma unroll
        for (int l = 0; l < 8; l++) {
            int e = t + l * 128;
            int row = e >> 4, d4 = (e & 15) * 4;
            const float* base = qkv + (size_t)(b * Sx + j0 + row) * 3072 + n * 64 + d4;
            float4 kv = *(const float4*)(base + 1024);
            kv.x = to_tf32(kv.x); kv.y = to_tf32(kv.y);
            kv.z = to_tf32(kv.z); kv.w = to_tf32(kv.w);
            *(float4*)&Ks[row * 68 + d4] = kv;
            float4 vv = *(const float4*)(base + 2048);
            vv.x = to_tf32(vv.x); vv.y = to_tf32(vv.y);
            vv.z = to_tf32(vv.z); vv.w = to_tf32(vv.w);
            *(float4*)&Vs[row * 72 + d4] = vv;
        }
        __syncthreads();

        float s[8][4];
#pragma unroll
        for (int nt = 0; nt < 8; nt++)
#pragma unroll
            for (int c = 0; c < 4; c++) s[nt][c] = 0.f;
#pragma unroll
        for (int kk = 0; kk < 8; kk++) {
            const int k = kk * 8;
            uint32_t a[4];
            a[0] = __float_as_uint(Qs[(r0    ) * 68 + k + q]);
            a[1] = __float_as_uint(Qs[(r0 + 8) * 68 + k + q]);
            a[2] = __float_as_uint(Qs[(r0    ) * 68 + k + q + 4]);
            a[3] = __float_as_uint(Qs[(r0 + 8) * 68 + k + q + 4]);
#pragma unroll
            for (int nt = 0; nt < 8; nt++) {
                uint32_t bfr[2];
                bfr[0] = __float_as_uint(Ks[(nt * 8 + g) * 68 + k + q]);
                bfr[1] = __float_as_uint(Ks[(nt * 8 + g) * 68 + k + q + 4]);
                mma_tf32(s[nt], a, bfr);
            }
        }

#pragma unroll
        for (int nt = 0; nt < 8; nt++) {
#pragma unroll
            for (int c = 0; c < 4; c++) {
                int i = (c < 2) ? rowA : rowB;
                int j = j0 + nt * 8 + 2 * q + (c & 1);
                bool allowed = (j <= i) && !((i >= spv) && (j < spv));
                s[nt][c] = allowed ? (s[nt][c] - slope2 * (float)(i - j)) : -1e30f;
            }
        }

        float mx0 = -1e30f, mx1 = -1e30f;
#pragma unroll
        for (int nt = 0; nt < 8; nt++) {
            mx0 = fmaxf(mx0, fmaxf(s[nt][0], s[nt][1]));
            mx1 = fmaxf(mx1, fmaxf(s[nt][2], s[nt][3]));
        }
        mx0 = fmaxf(mx0, __shfl_xor_sync(0xffffffffu, mx0, 1));
        mx0 = fmaxf(mx0, __shfl_xor_sync(0xffffffffu, mx0, 2));
        mx1 = fmaxf(mx1, __shfl_xor_sync(0xffffffffu, mx1, 1));
        mx1 = fmaxf(mx1, __shfl_xor_sync(0xffffffffu, mx1, 2));
        float mn0 = fmaxf(m0, mx0), mn1 = fmaxf(m1, mx1);
        float al0 = ex2(m0 - mn0), al1 = ex2(m1 - mn1);

        float sum0 = 0.f, sum1 = 0.f;
#pragma unroll
        for (int nt = 0; nt < 8; nt++) {
            float p0 = ex2(s[nt][0] - mn0);
            float p1 = ex2(s[nt][1] - mn0);
            float p2 = ex2(s[nt][2] - mn1);
            float p3 = ex2(s[nt][3] - mn1);
            sum0 += p0 + p1; sum1 += p2 + p3;
            float2 lo2; lo2.x = to_tf32(p0); lo2.y = to_tf32(p1);
            *(float2*)&Ps[(r0    ) * 68 + nt * 8 + 2 * q] = lo2;
            float2 hi2; hi2.x = to_tf32(p2); hi2.y = to_tf32(p3);
            *(float2*)&Ps[(r0 + 8) * 68 + nt * 8 + 2 * q] = hi2;
        }
        sum0 += __shfl_xor_sync(0xffffffffu, sum0, 1);
        sum0 += __shfl_xor_sync(0xffffffffu, sum0, 2);
        sum1 += __shfl_xor_sync(0xffffffffu, sum1, 1);
        sum1 += __shfl_xor_sync(0xffffffffu, sum1, 2);
        l0 = l0 * al0 + sum0;
        l1 = l1 * al1 + sum1;
        m0 = mn0; m1 = mn1;
#pragma unroll
        for (int nt = 0; nt < 8; nt++) {
            o[nt][0] *= al0; o[nt][1] *= al0;
            o[nt][2] *= al1; o[nt][3] *= al1;
        }
        __syncwarp();

#pragma unroll
        for (int kk = 0; kk < 8; kk++) {
            const int k = kk * 8;
            uint32_t a[4];
            a[0] = __float_as_uint(Ps[(r0    ) * 68 + k + q]);
            a[1] = __float_as_uint(Ps[(r0 + 8) * 68 + k + q]);
            a[2] = __float_as_uint(Ps[(r0    ) * 68 + k + q + 4]);
            a[3] = __float_as_uint(Ps[(r0 + 8) * 68 + k + q + 4]);
#pragma unroll
            for (int nt = 0; nt < 8; nt++) {
                uint32_t bfr[2];
                bfr[0] = __float_as_uint(Vs[(k + q    ) * 72 + nt * 8 + g]);
                bfr[1] = __float_as_uint(Vs[(k + q + 4) * 72 + nt * 8 + g]);
                mma_tf32(o[nt], a, bfr);
            }
        }
    }

    const float inv0 = 1.0f / l0, inv1 = 1.0f / l1;
#pragma unroll
    for (int nt = 0; nt < 8; nt++) {
        float2 v0; v0.x = o[nt][0] * inv0; v0.y = o[nt][1] * inv0;
        *(float2*)(attn + (size_t)(b * Sx + rowA) * Hx + n * 64 + nt * 8 + 2 * q) = v0;
        float2 v1; v1.x = o[nt][2] * inv1; v1.y = o[nt][3] * inv1;
        *(float2*)(attn + (size_t)(b * Sx + rowB) * Hx + n * 64 + nt * 8 + 2 * q) = v1;
    }
}

// ---------------- 3xTF32 logits GEMM (unchanged) ----------------
__global__ __launch_bounds__(128) void gemm_logits(const float* __restrict__ A,
                                                   const float* __restrict__ Bm,
                                                   float* __restrict__ C,
                                                   int M, int N, int K) {
    __shared__ float Ah[64 * 36], Al[64 * 36];
    __shared__ float Bh[32 * 72], Bl[32 * 72];
    const int t = threadIdx.x;
    const int warp = t >> 5, lane = t & 31;
    const int g = lane >> 2, q = lane & 3;
    const int wm = warp >> 1, wn = warp & 1;
    const int m0 = blockIdx.y * 64, n0 = blockIdx.x * 64;

    float acc[2][4][4];
#pragma unroll
    for (int mt = 0; mt < 2; mt++)
#pragma unroll
        for (int nt = 0; nt < 4; nt++)
#pragma unroll
            for (int r = 0; r < 4; r++) acc[mt][nt][r] = 0.f;

    for (int k0 = 0; k0 < K; k0 += 32) {
        {
            int row = t >> 1, c4 = (t & 1) * 16;
#pragma unroll
            for (int p = 0; p < 4; p++) {
                float4 v = *(const float4*)(A + (size_t)(m0 + row) * K + k0 + c4 + p * 4);
                float4 hi, lo;
                hi.x = to_tf32(v.x); lo.x = to_tf32(v.x - hi.x);
                hi.y = to_tf32(v.y); lo.y = to_tf32(v.y - hi.y);
                hi.z = to_tf32(v.z); lo.z = to_tf32(v.z - hi.z);
                hi.w = to_tf32(v.w); lo.w = to_tf32(v.w - hi.w);
                *(float4*)&Ah[row * 36 + c4 + p * 4] = hi;
                *(float4*)&Al[row * 36 + c4 + p * 4] = lo;
            }
        }
        {
#pragma unroll
            for (int p = 0; p < 4; p++) {
                int e = t + p * 128;
                int row = e & 63, c4 = (e >> 6) * 4;
                float4 v = *(const float4*)(Bm + (size_t)(n0 + row) * K + k0 + c4);
                float hv, lv;
                hv = to_tf32(v.x); lv = to_tf32(v.x - hv);
                Bh[(c4 + 0) * 72 + row] = hv; Bl[(c4 + 0) * 72 + row] = lv;
                hv = to_tf32(v.y); lv = to_tf32(v.y - hv);
                Bh[(c4 + 1) * 72 + row] = hv; Bl[(c4 + 1) * 72 + row] = lv;
                hv = to_tf32(v.z); lv = to_tf32(v.z - hv);
                Bh[(c4 + 2) * 72 + row] = hv; Bl[(c4 + 2) * 72 + row] = lv;
                hv = to_tf32(v.w); lv = to_tf32(v.w - hv);
                Bh[(c4 + 3) * 72 + row] = hv; Bl[(c4 + 3) * 72 + row] = lv;
            }
        }
        __syncthreads();

#pragma unroll
        for (int ks = 0; ks < 4; ks++) {
            const int k = ks * 8;
            uint32_t ah[2][4], al[2][4], bh[4][2], bl[4][2];
#pragma unroll
            for (int mt = 0; mt < 2; mt++) {
                int r = wm * 32 + mt * 16 + g;
                ah[mt][0] = __float_as_uint(Ah[(r    ) * 36 + k + q]);
                ah[mt][1] = __float_as_uint(Ah[(r + 8) * 36 + k + q]);
                ah[mt][2] = __float_as_uint(Ah[(r    ) * 36 + k + q + 4]);
                ah[mt][3] = __float_as_uint(Ah[(r + 8) * 36 + k + q + 4]);
                al[mt][0] = __float_as_uint(Al[(r    ) * 36 + k + q]);
                al[mt][1] = __float_as_uint(Al[(r + 8) * 36 + k + q]);
                al[mt][2] = __float_as_uint(Al[(r    ) * 36 + k + q + 4]);
                al[mt][3] = __float_as_uint(Al[(r + 8) * 36 + k + q + 4]);
            }
#pragma unroll
            for (int nt = 0; nt < 4; nt++) {
                int nn = wn * 32 + nt * 8 + g;
                bh[nt][0] = __float_as_uint(Bh[(k + q    ) * 72 + nn]);
                bh[nt][1] = __float_as_uint(Bh[(k + q + 4) * 72 + nn]);
                bl[nt][0] = __float_as_uint(Bl[(k + q    ) * 72 + nn]);
                bl[nt][1] = __float_as_uint(Bl[(k + q + 4) * 72 + nn]);
            }
#pragma unroll
            for (int mt = 0; mt < 2; mt++)
#pragma unroll
                for (int nt = 0; nt < 4; nt++) {
                    mma_tf32(acc[mt][nt], ah[mt], bl[nt]);
                    mma_tf32(acc[mt][nt], al[mt], bh[nt]);
                    mma_tf32(acc[mt][nt], ah[mt], bh[nt]);
                }
        }
        __syncthreads();
    }

#pragma unroll
    for (int mt = 0; mt < 2; mt++) {
#pragma unroll
        for (int nt = 0; nt < 4; nt++) {
            int r0 = m0 + wm * 32 + mt * 16 + g;
            int c0 = n0 + wn * 32 + nt * 8 + q * 2;
#pragma unroll
            for (int half_i = 0; half_i < 2; half_i++) {
                int row = r0 + half_i * 8;
                float2 o2;
                o2.x = acc[mt][nt][half_i * 2 + 0];
                o2.y = acc[mt][nt][half_i * 2 + 1];
                *(float2*)(C + (size_t)row * N + c0) = o2;
            }
        }
    }
}

// ---------------- launcher ----------------
extern "C" void kernel_launch(void* const* d_in, const int* in_sizes, int n_in,
                              void* d_out, int out_size) {
    const int*   ids    = (const int*)d_in[0];
    const int*   sp     = (const int*)d_in[1];
    const float* emb    = (const float*)d_in[2];
    const float* ln1_g  = (const float*)d_in[3];
    const float* ln1_b  = (const float*)d_in[4];
    const float* Wqkv   = (const float*)d_in[5];
    const float* bqkv   = (const float*)d_in[6];
    const float* Wo     = (const float*)d_in[7];
    const float* bo     = (const float*)d_in[8];
    const float* ln2_g  = (const float*)d_in[9];
    const float* ln2_b  = (const float*)d_in[10];
    const float* Wfc    = (const float*)d_in[11];
    const float* bfc    = (const float*)d_in[12];
    const float* Wproj  = (const float*)d_in[13];
    const float* bproj  = (const float*)d_in[14];
    const float* lnf_g  = (const float*)d_in[15];
    const float* lnf_b  = (const float*)d_in[16];
    float* out = (float*)d_out;

    float *x, *h, *qkv, *attn, *mid;
    cudaGetSymbolAddress((void**)&x,    g_x);
    cudaGetSymbolAddress((void**)&h,    g_h);
    cudaGetSymbolAddress((void**)&qkv,  g_qkv);
    cudaGetSymbolAddress((void**)&attn, g_attn);
    cudaGetSymbolAddress((void**)&mid,  g_mid);

    const int attn_smem = ATTN_SMEM_FLOATS * 4;
    cudaFuncSetAttribute(attn_kernel, cudaFuncAttributeMaxDynamicSharedMemorySize, attn_smem);

    embed_kernel<<<Mx, 256>>>(ids, emb, x);

    for (int l = 0; l < NLx; l++) {
        ln_kernel<<<Mx, 256>>>(x, ln1_g + l * Hx, ln1_b + l * Hx, h);
        gemm_h<false, false><<<dim3(3 * Hx / 128, Mx / 128), 256>>>(
            h, Wqkv + (size_t)l * Hx * 3 * Hx, bqkv + (size_t)l * 3 * Hx, nullptr, qkv,
            Mx, 3 * Hx, Hx);
        attn_kernel<<<dim3(Sx / 64, Bx * NHx), 128, attn_smem>>>(qkv, sp, attn);
        gemm_h<false, true><<<dim3(Hx / 128, Mx / 128), 256>>>(
            attn, Wo + (size_t)l * Hx * Hx, bo + (size_t)l * Hx, x, x, Mx, Hx, Hx);
        ln_kernel<<<Mx, 256>>>(x, ln2_g + l * Hx, ln2_b + l * Hx, h);
        gemm_h<true, false><<<dim3(Fx / 128, Mx / 128), 256>>>(
            h, Wfc + (size_t)l * Hx * Fx, bfc + (size_t)l * Fx, nullptr, mid,
            Mx, Fx, Hx);
        gemm_h<false, true><<<dim3(Hx / 128, Mx / 128), 256>>>(
            mid, Wproj + (size_t)l * Fx * Hx, bproj + (size_t)l * Hx, x, x, Mx, Hx, Fx);
    }

    ln_kernel<<<Mx, 256>>>(x, lnf_g, lnf_b, h);
    gemm_logits<<<dim3(Vx / 64, Mx / 64), 128>>>(h, emb, out, Mx, Vx, Hx);
}

// round 7
// speedup vs baseline: 1.5978x; 1.5978x over previous
#include <cuda_runtime.h>
#include <cuda_fp16.h>
#include <math.h>
#include <stdint.h>

#define Bx  16
#define Sx  512
#define Vx  512
#define Hx  1024
#define NLx 8
#define NHx 16
#define DHx 64
#define Fx  4096
#define Mx  (Bx*Sx)

#define LOG2E 1.4426950408889634f

// ---------------- scratch ----------------
__device__ float g_x[Mx*Hx];
__device__ float g_h[Mx*Hx];           // f32 h (final LN -> logits only)
__device__ float g_qkv[Mx*3*Hx];
__device__ half  g_hh[Mx*Hx];          // half h (per-layer LN output)
__device__ half  g_attn_h[Mx*Hx];
__device__ half  g_mid_h[(size_t)Mx*Fx];
// pre-transposed half weights, [N][K] per layer
__device__ half  g_Wqkv_t[(size_t)NLx*3*Hx*Hx];
__device__ half  g_Wo_t[(size_t)NLx*Hx*Hx];
__device__ half  g_Wfc_t[(size_t)NLx*Fx*Hx];
__device__ half  g_Wproj_t[(size_t)NLx*Hx*Fx];

// ---------------- helpers ----------------
__device__ __forceinline__ float to_tf32(float x) {
    float r;
    asm("cvt.rna.tf32.f32 %0, %1;" : "=f"(r) : "f"(x));
    return r;
}
__device__ __forceinline__ float ex2(float x) {
    float r;
    asm("ex2.approx.f32 %0, %1;" : "=f"(r) : "f"(x));
    return r;
}
__device__ __forceinline__ void mma_tf32(float* c, const uint32_t* a, const uint32_t* b) {
    asm volatile(
        "mma.sync.aligned.m16n8k8.row.col.f32.tf32.tf32.f32 "
        "{%0,%1,%2,%3}, {%4,%5,%6,%7}, {%8,%9}, {%0,%1,%2,%3};\n"
        : "+f"(c[0]), "+f"(c[1]), "+f"(c[2]), "+f"(c[3])
        : "r"(a[0]), "r"(a[1]), "r"(a[2]), "r"(a[3]), "r"(b[0]), "r"(b[1]));
}
__device__ __forceinline__ void mma_f16(float* c, const uint32_t* a, const uint32_t* b) {
    asm volatile(
        "mma.sync.aligned.m16n8k16.row.col.f32.f16.f16.f32 "
        "{%0,%1,%2,%3}, {%4,%5,%6,%7}, {%8,%9}, {%0,%1,%2,%3};\n"
        : "+f"(c[0]), "+f"(c[1]), "+f"(c[2]), "+f"(c[3])
        : "r"(a[0]), "r"(a[1]), "r"(a[2]), "r"(a[3]), "r"(b[0]), "r"(b[1]));
}
__device__ __forceinline__ void cp_async16(void* smem_dst, const void* gmem_src) {
    uint32_t s = (uint32_t)__cvta_generic_to_shared(smem_dst);
    asm volatile("cp.async.cg.shared.global [%0], [%1], 16;\n" :: "r"(s), "l"(gmem_src));
}
__device__ __forceinline__ void cp_commit() { asm volatile("cp.async.commit_group;\n"); }
__device__ __forceinline__ void cp_wait2() { asm volatile("cp.async.wait_group 2;\n"); }
__device__ __forceinline__ float gelu_f(float v) {
    return 0.5f * v * (1.0f + tanhf(0.7978845608028654f * (v + 0.044715f * v * v * v)));
}

// ---------------- weight transpose+convert: W[K,N] f32 -> Wt[N,K] half ------
__global__ __launch_bounds__(256) void wtrans_kernel(const float* __restrict__ W,
                                                     half* __restrict__ Wt,
                                                     int K, int N) {
    __shared__ float tile[32][33];
    const size_t lsz = (size_t)K * N;
    const float* Wl = W + blockIdx.z * lsz;
    half* Wtl = Wt + blockIdx.z * lsz;
    int n0 = blockIdx.x * 32, k0 = blockIdx.y * 32;
    int tx = threadIdx.x & 31, ty = threadIdx.x >> 5;   // 32 x 8
#pragma unroll
    for (int i = 0; i < 4; i++)
        tile[ty + i * 8][tx] = Wl[(size_t)(k0 + ty + i * 8) * N + n0 + tx];
    __syncthreads();
#pragma unroll
    for (int i = 0; i < 4; i++)
        Wtl[(size_t)(n0 + ty + i * 8) * K + k0 + tx] = __float2half_rn(tile[tx][ty + i * 8]);
}

// ---------------- embedding ----------------
__global__ __launch_bounds__(256) void embed_kernel(const int* __restrict__ ids,
                                                    const float* __restrict__ emb,
                                                    float* __restrict__ out) {
    int m = blockIdx.x, t = threadIdx.x;
    int id = ids[m];
    ((float4*)(out + (size_t)m * Hx))[t] = ((const float4*)(emb + (size_t)id * Hx))[t];
}

// ---------------- layernorm: HALF_OUT writes half, else f32 ----------------
template<bool HALF_OUT>
__global__ __launch_bounds__(256) void ln_kernel(const float* __restrict__ x,
                                                 const float* __restrict__ g,
                                                 const float* __restrict__ b,
                                                 float* __restrict__ outf,
                                                 half* __restrict__ outh) {
    int m = blockIdx.x, t = threadIdx.x;
    __shared__ float red[8];
    float4 v = ((const float4*)(x + (size_t)m * Hx))[t];

    float s = v.x + v.y + v.z + v.w;
#pragma unroll
    for (int o = 16; o; o >>= 1) s += __shfl_xor_sync(0xffffffffu, s, o);
    if ((t & 31) == 0) red[t >> 5] = s;
    __syncthreads();
    float mu = 0.f;
#pragma unroll
    for (int w = 0; w < 8; w++) mu += red[w];
    mu *= (1.0f / Hx);
    __syncthreads();

    float d0 = v.x - mu, d1 = v.y - mu, d2 = v.z - mu, d3 = v.w - mu;
    float s2 = d0*d0 + d1*d1 + d2*d2 + d3*d3;
#pragma unroll
    for (int o = 16; o; o >>= 1) s2 += __shfl_xor_sync(0xffffffffu, s2, o);
    if ((t & 31) == 0) red[t >> 5] = s2;
    __syncthreads();
    float var = 0.f;
#pragma unroll
    for (int w = 0; w < 8; w++) var += red[w];
    var *= (1.0f / Hx);
    float inv = rsqrtf(var + 1e-5f);

    float4 gg = ((const float4*)g)[t];
    float4 bb = ((const float4*)b)[t];
    float o0 = d0 * inv * gg.x + bb.x;
    float o1 = d1 * inv * gg.y + bb.y;
    float o2 = d2 * inv * gg.z + bb.z;
    float o3 = d3 * inv * gg.w + bb.w;
    if (HALF_OUT) {
        half2 h0 = __floats2half2_rn(o0, o1);
        half2 h1 = __floats2half2_rn(o2, o3);
        *(half2*)(outh + (size_t)m * Hx + t * 4) = h0;
        *(half2*)(outh + (size_t)m * Hx + t * 4 + 2) = h1;
    } else {
        float4 o4; o4.x = o0; o4.y = o1; o4.z = o2; o4.w = o3;
        ((float4*)(outf + (size_t)m * Hx))[t] = o4;
    }
}

// ======= fp16 tensor-core GEMM, 4-stage cp.async =============================
// A: half [M,K] K-major. B: half [N,K] K-major (pre-transposed weights).
// CTA tile 128x128x32, 8 warps, 32x64 warp tile. Stride-40 half smem rows
// (80B: 16B-aligned, frag banks (20g+q) distinct). No cvt/LDG in mainloop.
#define HST 40
#define NSTAGE 4
#define STG_HALVES (128 * HST)            // per-operand per-stage halves
#define GEMM_SMEM (NSTAGE * 2 * STG_HALVES * 2)   // bytes = 81920

template<bool GELU, bool RESID, bool OUT_HALF>
__global__ __launch_bounds__(256, 2) void gemm_h16(const half* __restrict__ A,
                                                   const half* __restrict__ Bw,
                                                   const float* __restrict__ bias,
                                                   const float* __restrict__ R,
                                                   float* __restrict__ C,
                                                   half* __restrict__ Ch,
                                                   int M, int N, int K) {
    extern __shared__ half smh[];
    const int t = threadIdx.x;
    const int warp = t >> 5, lane = t & 31;
    const int g = lane >> 2, q = lane & 3;
    const int wm = warp >> 1, wn = warp & 1;
    const int m0 = blockIdx.y * 128, n0 = blockIdx.x * 128;

    const int f_row = t >> 1, f_ch = (t & 1) * 16;   // fill: row, k-half-offset

    float acc[2][8][4];
#pragma unroll
    for (int mt = 0; mt < 2; mt++)
#pragma unroll
        for (int nt = 0; nt < 8; nt++)
#pragma unroll
            for (int r = 0; r < 4; r++) acc[mt][nt][r] = 0.f;

    const half* Arow = A + (size_t)(m0 + f_row) * K + f_ch;
    const half* Brow = Bw + (size_t)(n0 + f_row) * K + f_ch;

    // prologue: stages 0..2
#pragma unroll
    for (int s = 0; s < NSTAGE - 1; s++) {
        half* as = smh + s * 2 * STG_HALVES;
        half* bs = as + STG_HALVES;
        cp_async16(&as[f_row * HST + f_ch],     Arow + s * 32);
        cp_async16(&as[f_row * HST + f_ch + 8], Arow + s * 32 + 8);
        cp_async16(&bs[f_row * HST + f_ch],     Brow + s * 32);
        cp_async16(&bs[f_row * HST + f_ch + 8], Brow + s * 32 + 8);
        cp_commit();
    }

    const int T = K >> 5;
    for (int i = 0; i < T; i++) {
        const int s = i & (NSTAGE - 1);
        cp_wait2();
        __syncthreads();

        if (i + NSTAGE - 1 < T) {
            const int sn = (i + NSTAGE - 1) & (NSTAGE - 1);
            const int kn = (i + NSTAGE - 1) * 32;
            half* as = smh + sn * 2 * STG_HALVES;
            half* bs = as + STG_HALVES;
            cp_async16(&as[f_row * HST + f_ch],     Arow + kn);
            cp_async16(&as[f_row * HST + f_ch + 8], Arow + kn + 8);
            cp_async16(&bs[f_row * HST + f_ch],     Brow + kn);
            cp_async16(&bs[f_row * HST + f_ch + 8], Brow + kn + 8);
        }
        cp_commit();

        const half* As = smh + s * 2 * STG_HALVES;
        const half* Bs = As + STG_HALVES;
#pragma unroll
        for (int ks = 0; ks < 2; ks++) {
            const int k = ks * 16;
            uint32_t af[2][4], bf[8][2];
#pragma unroll
            for (int mt = 0; mt < 2; mt++) {
                int r = wm * 32 + mt * 16 + g;
                af[mt][0] = *(const uint32_t*)&As[(r    ) * HST + k + 2 * q];
                af[mt][1] = *(const uint32_t*)&As[(r + 8) * HST + k + 2 * q];
                af[mt][2] = *(const uint32_t*)&As[(r    ) * HST + k + 2 * q + 8];
                af[mt][3] = *(const uint32_t*)&As[(r + 8) * HST + k + 2 * q + 8];
            }
#pragma unroll
            for (int nt = 0; nt < 8; nt++) {
                int n = wn * 64 + nt * 8 + g;
                bf[nt][0] = *(const uint32_t*)&Bs[n * HST + k + 2 * q];
                bf[nt][1] = *(const uint32_t*)&Bs[n * HST + k + 2 * q + 8];
            }
#pragma unroll
            for (int mt = 0; mt < 2; mt++)
#pragma unroll
                for (int nt = 0; nt < 8; nt++)
                    mma_f16(acc[mt][nt], af[mt], bf[nt]);
        }
        __syncthreads();
    }

    // ---- epilogue
#pragma unroll
    for (int mt = 0; mt < 2; mt++) {
#pragma unroll
        for (int nt = 0; nt < 8; nt++) {
            int r0 = m0 + wm * 32 + mt * 16 + g;
            int c0 = n0 + wn * 64 + nt * 8 + q * 2;
            float b0 = bias ? bias[c0] : 0.f;
            float b1 = bias ? bias[c0 + 1] : 0.f;
#pragma unroll
            for (int hf = 0; hf < 2; hf++) {
                int row = r0 + hf * 8;
                float v0 = acc[mt][nt][hf * 2 + 0] + b0;
                float v1 = acc[mt][nt][hf * 2 + 1] + b1;
                if (GELU) { v0 = gelu_f(v0); v1 = gelu_f(v1); }
                if (RESID) {
                    const float2 rr = *(const float2*)(R + (size_t)row * N + c0);
                    v0 += rr.x; v1 += rr.y;
                }
                if (OUT_HALF) {
                    *(half2*)(Ch + (size_t)row * N + c0) = __floats2half2_rn(v0, v1);
                } else {
                    float2 o2; o2.x = v0; o2.y = v1;
                    *(float2*)(C + (size_t)row * N + c0) = o2;
                }
            }
        }
    }
}

// ---------------- fused flash attention (tf32 mma; half output) -------------
#define ATTN_SMEM_FLOATS (64*68*3 + 64*72)

__global__ __launch_bounds__(128) void attn_kernel(const float* __restrict__ qkv,
                                                   const int* __restrict__ sp,
                                                   half* __restrict__ attn) {
    extern __shared__ float sm[];
    float* Qs = sm;
    float* Ks = Qs + 64 * 68;
    float* Vs = Ks + 64 * 68;
    float* Ps = Vs + 64 * 72;

    const int it = blockIdx.x, bn = blockIdx.y;
    const int b = bn >> 4, n = bn & 15;
    const int t = threadIdx.x, w = t >> 5, lane = t & 31;
    const int g = lane >> 2, q = lane & 3;
    const int i0 = it * 64;
    const int spv = sp[b];
    const float slope2 = exp2f(-0.5f * (float)(n + 1)) * LOG2E;
    const float qscale = 0.125f * LOG2E;

#pragma unroll
    for (int l = 0; l < 8; l++) {
        int e = t + l * 128;
        int row = e >> 4, d4 = (e & 15) * 4;
        float4 v = *(const float4*)(qkv + (size_t)(b * Sx + i0 + row) * 3072 + n * 64 + d4);
        v.x = to_tf32(v.x * qscale); v.y = to_tf32(v.y * qscale);
        v.z = to_tf32(v.z * qscale); v.w = to_tf32(v.w * qscale);
        *(float4*)&Qs[row * 68 + d4] = v;
    }

    float o[8][4];
#pragma unroll
    for (int nt = 0; nt < 8; nt++)
#pragma unroll
        for (int c = 0; c < 4; c++) o[nt][c] = 0.f;
    float m0 = -1e30f, m1 = -1e30f, l0 = 0.f, l1 = 0.f;

    const int r0 = w * 16 + g;
    const int rowA = i0 + r0, rowB = rowA + 8;

    for (int jt = 0; jt <= it; jt++) {
        const int j0 = jt * 64;
        __syncthreads();
#pragma unroll
        for (int l = 0; l < 8; l++) {
            int e = t + l * 128;
            int row = e >> 4, d4 = (e & 15) * 4;
            const float* base = qkv + (size_t)(b * Sx + j0 + row) * 3072 + n * 64 + d4;
            float4 kv = *(const float4*)(base + 1024);
            kv.x = to_tf32(kv.x); kv.y = to_tf32(kv.y);
            kv.z = to_tf32(kv.z); kv.w = to_tf32(kv.w);
            *(float4*)&Ks[row * 68 + d4] = kv;
            float4 vv = *(const float4*)(base + 2048);
            vv.x = to_tf32(vv.x); vv.y = to_tf32(vv.y);
            vv.z = to_tf32(vv.z); vv.w = to_tf32(vv.w);
            *(float4*)&Vs[row * 72 + d4] = vv;
        }
        __syncthreads();

        float s[8][4];
#pragma unroll
        for (int nt = 0; nt < 8; nt++)
#pragma unroll
            for (int c = 0; c < 4; c++) s[nt][c] = 0.f;
#pragma unroll
        for (int kk = 0; kk < 8; kk++) {
            const int k = kk * 8;
            uint32_t a[4];
            a[0] = __float_as_uint(Qs[(r0    ) * 68 + k + q]);
            a[1] = __float_as_uint(Qs[(r0 + 8) * 68 + k + q]);
            a[2] = __float_as_uint(Qs[(r0    ) * 68 + k + q + 4]);
            a[3] = __float_as_uint(Qs[(r0 + 8) * 68 + k + q + 4]);
#pragma unroll
            for (int nt = 0; nt < 8; nt++) {
                uint32_t bfr[2];
                bfr[0] = __float_as_uint(Ks[(nt * 8 + g) * 68 + k + q]);
                bfr[1] = __float_as_uint(Ks[(nt * 8 + g) * 68 + k + q + 4]);
                mma_tf32(s[nt], a, bfr);
            }
        }

#pragma unroll
        for (int nt = 0; nt < 8; nt++) {
#pragma unroll
            for (int c = 0; c < 4; c++) {
                int i = (c < 2) ? rowA : rowB;
                int j = j0 + nt * 8 + 2 * q + (c & 1);
                bool allowed = (j <= i) && !((i >= spv) && (j < spv));
                s[nt][c] = allowed ? (s[nt][c] - slope2 * (float)(i - j)) : -1e30f;
            }
        }

        float mx0 = -1e30f, mx1 = -1e30f;
#pragma unroll
        for (int nt = 0; nt < 8; nt++) {
            mx0 = fmaxf(mx0, fmaxf(s[nt][0], s[nt][1]));
            mx1 = fmaxf(mx1, fmaxf(s[nt][2], s[nt][3]));
        }
        mx0 = fmaxf(mx0, __shfl_xor_sync(0xffffffffu, mx0, 1));
        mx0 = fmaxf(mx0, __shfl_xor_sync(0xffffffffu, mx0, 2));
        mx1 = fmaxf(mx1, __shfl_xor_sync(0xffffffffu, mx1, 1));
        mx1 = fmaxf(mx1, __shfl_xor_sync(0xffffffffu, mx1, 2));
        float mn0 = fmaxf(m0, mx0), mn1 = fmaxf(m1, mx1);
        float al0 = ex2(m0 - mn0), al1 = ex2(m1 - mn1);

        float sum0 = 0.f, sum1 = 0.f;
#pragma unroll
        for (int nt = 0; nt < 8; nt++) {
            float p0 = ex2(s[nt][0] - mn0);
            float p1 = ex2(s[nt][1] - mn0);
            float p2 = ex2(s[nt][2] - mn1);
            float p3 = ex2(s[nt][3] - mn1);
            sum0 += p0 + p1; sum1 += p2 + p3;
            float2 lo2; lo2.x = to_tf32(p0); lo2.y = to_tf32(p1);
            *(float2*)&Ps[(r0    ) * 68 + nt * 8 + 2 * q] = lo2;
            float2 hi2; hi2.x = to_tf32(p2); hi2.y = to_tf32(p3);
            *(float2*)&Ps[(r0 + 8) * 68 + nt * 8 + 2 * q] = hi2;
        }
        sum0 += __shfl_xor_sync(0xffffffffu, sum0, 1);
        sum0 += __shfl_xor_sync(0xffffffffu, sum0, 2);
        sum1 += __shfl_xor_sync(0xffffffffu, sum1, 1);
        sum1 += __shfl_xor_sync(0xffffffffu, sum1, 2);
        l0 = l0 * al0 + sum0;
        l1 = l1 * al1 + sum1;
        m0 = mn0; m1 = mn1;
#pragma unroll
        for (int nt = 0; nt < 8; nt++) {
            o[nt][0] *= al0; o[nt][1] *= al0;
            o[nt][2] *= al1; o[nt][3] *= al1;
        }
        __syncwarp();

#pragma unroll
        for (int kk = 0; kk < 8; kk++) {
            const int k = kk * 8;
            uint32_t a[4];
            a[0] = __float_as_uint(Ps[(r0    ) * 68 + k + q]);
            a[1] = __float_as_uint(Ps[(r0 + 8) * 68 + k + q]);
            a[2] = __float_as_uint(Ps[(r0    ) * 68 + k + q + 4]);
            a[3] = __float_as_uint(Ps[(r0 + 8) * 68 + k + q + 4]);
#pragma unroll
            for (int nt = 0; nt < 8; nt++) {
                uint32_t bfr[2];
                bfr[0] = __float_as_uint(Vs[(k + q    ) * 72 + nt * 8 + g]);
                bfr[1] = __float_as_uint(Vs[(k + q + 4) * 72 + nt * 8 + g]);
                mma_tf32(o[nt], a, bfr);
            }
        }
    }

    const float inv0 = 1.0f / l0, inv1 = 1.0f / l1;
#pragma unroll
    for (int nt = 0; nt < 8; nt++) {
        *(half2*)(attn + (size_t)(b * Sx + rowA) * Hx + n * 64 + nt * 8 + 2 * q) =
            __floats2half2_rn(o[nt][0] * inv0, o[nt][1] * inv0);
        *(half2*)(attn + (size_t)(b * Sx + rowB) * Hx + n * 64 + nt * 8 + 2 * q) =
            __floats2half2_rn(o[nt][2] * inv1, o[nt][3] * inv1);
    }
}

// ---------------- 3xTF32 logits GEMM (unchanged) ----------------
__global__ __launch_bounds__(128) void gemm_logits(const float* __restrict__ A,
                                                   const float* __restrict__ Bm,
                                                   float* __restrict__ C,
                                                   int M, int N, int K) {
    __shared__ float Ah[64 * 36], Al[64 * 36];
    __shared__ float Bh[32 * 72], Bl[32 * 72];
    const int t = threadIdx.x;
    const int warp = t >> 5, lane = t & 31;
    const int g = lane >> 2, q = lane & 3;
    const int wm = warp >> 1, wn = warp & 1;
    const int m0 = blockIdx.y * 64, n0 = blockIdx.x * 64;

    float acc[2][4][4];
#pragma unroll
    for (int mt = 0; mt < 2; mt++)
#pragma unroll
        for (int nt = 0; nt < 4; nt++)
#pragma unroll
            for (int r = 0; r < 4; r++) acc[mt][nt][r] = 0.f;

    for (int k0 = 0; k0 < K; k0 += 32) {
        {
            int row = t >> 1, c4 = (t & 1) * 16;
#pragma unroll
            for (int p = 0; p < 4; p++) {
                float4 v = *(const float4*)(A + (size_t)(m0 + row) * K + k0 + c4 + p * 4);
                float4 hi, lo;
                hi.x = to_tf32(v.x); lo.x = to_tf32(v.x - hi.x);
                hi.y = to_tf32(v.y); lo.y = to_tf32(v.y - hi.y);
                hi.z = to_tf32(v.z); lo.z = to_tf32(v.z - hi.z);
                hi.w = to_tf32(v.w); lo.w = to_tf32(v.w - hi.w);
                *(float4*)&Ah[row * 36 + c4 + p * 4] = hi;
                *(float4*)&Al[row * 36 + c4 + p * 4] = lo;
            }
        }
        {
#pragma unroll
            for (int p = 0; p < 4; p++) {
                int e = t + p * 128;
                int row = e & 63, c4 = (e >> 6) * 4;
                float4 v = *(const float4*)(Bm + (size_t)(n0 + row) * K + k0 + c4);
                float hv, lv;
                hv = to_tf32(v.x); lv = to_tf32(v.x - hv);
                Bh[(c4 + 0) * 72 + row] = hv; Bl[(c4 + 0) * 72 + row] = lv;
                hv = to_tf32(v.y); lv = to_tf32(v.y - hv);
                Bh[(c4 + 1) * 72 + row] = hv; Bl[(c4 + 1) * 72 + row] = lv;
                hv = to_tf32(v.z); lv = to_tf32(v.z - hv);
                Bh[(c4 + 2) * 72 + row] = hv; Bl[(c4 + 2) * 72 + row] = lv;
                hv = to_tf32(v.w); lv = to_tf32(v.w - hv);
                Bh[(c4 + 3) * 72 + row] = hv; Bl[(c4 + 3) * 72 + row] = lv;
            }
        }
        __syncthreads();

#pragma unroll
        for (int ks = 0; ks < 4; ks++) {
            const int k = ks * 8;
            uint32_t ah[2][4], al[2][4], bh[4][2], bl[4][2];
#pragma unroll
            for (int mt = 0; mt < 2; mt++) {
                int r = wm * 32 + mt * 16 + g;
                ah[mt][0] = __float_as_uint(Ah[(r    ) * 36 + k + q]);
                ah[mt][1] = __float_as_uint(Ah[(r + 8) * 36 + k + q]);
                ah[mt][2] = __float_as_uint(Ah[(r    ) * 36 + k + q + 4]);
                ah[mt][3] = __float_as_uint(Ah[(r + 8) * 36 + k + q + 4]);
                al[mt][0] = __float_as_uint(Al[(r    ) * 36 + k + q]);
                al[mt][1] = __float_as_uint(Al[(r + 8) * 36 + k + q]);
                al[mt][2] = __float_as_uint(Al[(r    ) * 36 + k + q + 4]);
                al[mt][3] = __float_as_uint(Al[(r + 8) * 36 + k + q + 4]);
            }
#pragma unroll
            for (int nt = 0; nt < 4; nt++) {
                int nn = wn * 32 + nt * 8 + g;
                bh[nt][0] = __float_as_uint(Bh[(k + q    ) * 72 + nn]);
                bh[nt][1] = __float_as_uint(Bh[(k + q + 4) * 72 + nn]);
                bl[nt][0] = __float_as_uint(Bl[(k + q    ) * 72 + nn]);
                bl[nt][1] = __float_as_uint(Bl[(k + q + 4) * 72 + nn]);
            }
#pragma unroll
            for (int mt = 0; mt < 2; mt++)
#pragma unroll
                for (int nt = 0; nt < 4; nt++) {
                    mma_tf32(acc[mt][nt], ah[mt], bl[nt]);
                    mma_tf32(acc[mt][nt], al[mt], bh[nt]);
                    mma_tf32(acc[mt][nt], ah[mt], bh[nt]);
                }
        }
        __syncthreads();
    }

#pragma unroll
    for (int mt = 0; mt < 2; mt++) {
#pragma unroll
        for (int nt = 0; nt < 4; nt++) {
            int r0 = m0 + wm * 32 + mt * 16 + g;
            int c0 = n0 + wn * 32 + nt * 8 + q * 2;
#pragma unroll
            for (int hf = 0; hf < 2; hf++) {
                int row = r0 + hf * 8;
                float2 o2;
                o2.x = acc[mt][nt][hf * 2 + 0];
                o2.y = acc[mt][nt][hf * 2 + 1];
                *(float2*)(C + (size_t)row * N + c0) = o2;
            }
        }
    }
}

// ---------------- launcher ----------------
extern "C" void kernel_launch(void* const* d_in, const int* in_sizes, int n_in,
                              void* d_out, int out_size) {
    const int*   ids    = (const int*)d_in[0];
    const int*   sp     = (const int*)d_in[1];
    const float* emb    = (const float*)d_in[2];
    const float* ln1_g  = (const float*)d_in[3];
    const float* ln1_b  = (const float*)d_in[4];
    const float* Wqkv   = (const float*)d_in[5];
    const float* bqkv   = (const float*)d_in[6];
    const float* Wo     = (const float*)d_in[7];
    const float* bo     = (const float*)d_in[8];
    const float* ln2_g  = (const float*)d_in[9];
    const float* ln2_b  = (const float*)d_in[10];
    const float* Wfc    = (const float*)d_in[11];
    const float* bfc    = (const float*)d_in[12];
    const float* Wproj  = (const float*)d_in[13];
    const float* bproj  = (const float*)d_in[14];
    const float* lnf_g  = (const float*)d_in[15];
    const float* lnf_b  = (const float*)d_in[16];
    float* out = (float*)d_out;

    float *x, *h, *qkv;
    half *hh, *attn_h, *mid_h, *wqkv_t, *wo_t, *wfc_t, *wproj_t;
    cudaGetSymbolAddress((void**)&x,       g_x);
    cudaGetSymbolAddress((void**)&h,       g_h);
    cudaGetSymbolAddress((void**)&qkv,     g_qkv);
    cudaGetSymbolAddress((void**)&hh,      g_hh);
    cudaGetSymbolAddress((void**)&attn_h,  g_attn_h);
    cudaGetSymbolAddress((void**)&mid_h,   g_mid_h);
    cudaGetSymbolAddress((void**)&wqkv_t,  g_Wqkv_t);
    cudaGetSymbolAddress((void**)&wo_t,    g_Wo_t);
    cudaGetSymbolAddress((void**)&wfc_t,   g_Wfc_t);
    cudaGetSymbolAddress((void**)&wproj_t, g_Wproj_t);

    const int attn_smem = ATTN_SMEM_FLOATS * 4;
    cudaFuncSetAttribute(attn_kernel, cudaFuncAttributeMaxDynamicSharedMemorySize, attn_smem);
    cudaFuncSetAttribute(gemm_h16<false, false, false>, cudaFuncAttributeMaxDynamicSharedMemorySize, GEMM_SMEM);
    cudaFuncSetAttribute(gemm_h16<false, true, false>,  cudaFuncAttributeMaxDynamicSharedMemorySize, GEMM_SMEM);
    cudaFuncSetAttribute(gemm_h16<true, false, true>,   cudaFuncAttributeMaxDynamicSharedMemorySize, GEMM_SMEM);

    // ---- one-time-per-launch weight transpose+convert (graph-capturable)
    wtrans_kernel<<<dim3(3 * Hx / 32, Hx / 32, NLx), 256>>>(Wqkv, wqkv_t, Hx, 3 * Hx);
    wtrans_kernel<<<dim3(Hx / 32, Hx / 32, NLx), 256>>>(Wo, wo_t, Hx, Hx);
    wtrans_kernel<<<dim3(Fx / 32, Hx / 32, NLx), 256>>>(Wfc, wfc_t, Hx, Fx);
    wtrans_kernel<<<dim3(Hx / 32, Fx / 32, NLx), 256>>>(Wproj, wproj_t, Fx, Hx);

    embed_kernel<<<Mx, 256>>>(ids, emb, x);

    for (int l = 0; l < NLx; l++) {
        ln_kernel<true><<<Mx, 256>>>(x, ln1_g + l * Hx, ln1_b + l * Hx, nullptr, hh);
        gemm_h16<false, false, false><<<dim3(3 * Hx / 128, Mx / 128), 256, GEMM_SMEM>>>(
            hh, wqkv_t + (size_t)l * 3 * Hx * Hx, bqkv + (size_t)l * 3 * Hx, nullptr,
            qkv, nullptr, Mx, 3 * Hx, Hx);
        attn_kernel<<<dim3(Sx / 64, Bx * NHx), 128, attn_smem>>>(qkv, sp, attn_h);
        gemm_h16<false, true, false><<<dim3(Hx / 128, Mx / 128), 256, GEMM_SMEM>>>(
            attn_h, wo_t + (size_t)l * Hx * Hx, bo + (size_t)l * Hx, x,
            x, nullptr, Mx, Hx, Hx);
        ln_kernel<true><<<Mx, 256>>>(x, ln2_g + l * Hx, ln2_b + l * Hx, nullptr, hh);
        gemm_h16<true, false, true><<<dim3(Fx / 128, Mx / 128), 256, GEMM_SMEM>>>(
            hh, wfc_t + (size_t)l * Fx * Hx, bfc + (size_t)l * Fx, nullptr,
            nullptr, mid_h, Mx, Fx, Hx);
        gemm_h16<false, true, false><<<dim3(Hx / 128, Mx / 128), 256, GEMM_SMEM>>>(
            mid_h, wproj_t + (size_t)l * Hx * Fx, bproj + (size_t)l * Hx, x,
            x, nullptr, Mx, Hx, Fx);
    }

    ln_kernel<false><<<Mx, 256>>>(x, lnf_g, lnf_b, h, nullptr);
    gemm_logits<<<dim3(Vx / 64, Mx / 64), 128>>>(h, emb, out, Mx, Vx, Hx);
}

// round 8
// speedup vs baseline: 1.8649x; 1.1672x over previous
#include <cuda_runtime.h>
#include <cuda_fp16.h>
#include <math.h>
#include <stdint.h>

#define Bx  16
#define Sx  512
#define Vx  512
#define Hx  1024
#define NLx 8
#define NHx 16
#define DHx 64
#define Fx  4096
#define Mx  (Bx*Sx)

#define LOG2E 1.4426950408889634f

// ---------------- scratch ----------------
__device__ float g_x[Mx*Hx];
__device__ float g_h[Mx*Hx];
__device__ float g_qkv[Mx*3*Hx];
__device__ half  g_hh[Mx*Hx];
__device__ half  g_attn_h[Mx*Hx];
__device__ half  g_mid_h[(size_t)Mx*Fx];
__device__ half  g_Wqkv_t[(size_t)NLx*3*Hx*Hx];
__device__ half  g_Wo_t[(size_t)NLx*Hx*Hx];
__device__ half  g_Wfc_t[(size_t)NLx*Fx*Hx];
__device__ half  g_Wproj_t[(size_t)NLx*Hx*Fx];

// ---------------- helpers ----------------
__device__ __forceinline__ float to_tf32(float x) {
    float r;
    asm("cvt.rna.tf32.f32 %0, %1;" : "=f"(r) : "f"(x));
    return r;
}
__device__ __forceinline__ float ex2(float x) {
    float r;
    asm("ex2.approx.f32 %0, %1;" : "=f"(r) : "f"(x));
    return r;
}
__device__ __forceinline__ void mma_tf32(float* c, const uint32_t* a, const uint32_t* b) {
    asm volatile(
        "mma.sync.aligned.m16n8k8.row.col.f32.tf32.tf32.f32 "
        "{%0,%1,%2,%3}, {%4,%5,%6,%7}, {%8,%9}, {%0,%1,%2,%3};\n"
        : "+f"(c[0]), "+f"(c[1]), "+f"(c[2]), "+f"(c[3])
        : "r"(a[0]), "r"(a[1]), "r"(a[2]), "r"(a[3]), "r"(b[0]), "r"(b[1]));
}
__device__ __forceinline__ void mma_f16(float* c, const uint32_t* a, const uint32_t* b) {
    asm volatile(
        "mma.sync.aligned.m16n8k16.row.col.f32.f16.f16.f32 "
        "{%0,%1,%2,%3}, {%4,%5,%6,%7}, {%8,%9}, {%0,%1,%2,%3};\n"
        : "+f"(c[0]), "+f"(c[1]), "+f"(c[2]), "+f"(c[3])
        : "r"(a[0]), "r"(a[1]), "r"(a[2]), "r"(a[3]), "r"(b[0]), "r"(b[1]));
}
__device__ __forceinline__ void ldsm_x4(uint32_t& r0, uint32_t& r1, uint32_t& r2, uint32_t& r3,
                                        uint32_t addr) {
    asm volatile("ldmatrix.sync.aligned.m8n8.x4.shared.b16 {%0,%1,%2,%3}, [%4];"
                 : "=r"(r0), "=r"(r1), "=r"(r2), "=r"(r3) : "r"(addr));
}
__device__ __forceinline__ void cp_async16(void* smem_dst, const void* gmem_src) {
    uint32_t s = (uint32_t)__cvta_generic_to_shared(smem_dst);
    asm volatile("cp.async.cg.shared.global [%0], [%1], 16;\n" :: "r"(s), "l"(gmem_src));
}
__device__ __forceinline__ void cp_commit() { asm volatile("cp.async.commit_group;\n"); }
__device__ __forceinline__ void cp_wait2() { asm volatile("cp.async.wait_group 2;\n"); }
__device__ __forceinline__ float gelu_f(float v) {
    return 0.5f * v * (1.0f + tanhf(0.7978845608028654f * (v + 0.044715f * v * v * v)));
}

// ---------------- weight transpose+convert ----------------
__global__ __launch_bounds__(256) void wtrans_kernel(const float* __restrict__ W,
                                                     half* __restrict__ Wt,
                                                     int K, int N) {
    __shared__ float tile[32][33];
    const size_t lsz = (size_t)K * N;
    const float* Wl = W + blockIdx.z * lsz;
    half* Wtl = Wt + blockIdx.z * lsz;
    int n0 = blockIdx.x * 32, k0 = blockIdx.y * 32;
    int tx = threadIdx.x & 31, ty = threadIdx.x >> 5;
#pragma unroll
    for (int i = 0; i < 4; i++)
        tile[ty + i * 8][tx] = Wl[(size_t)(k0 + ty + i * 8) * N + n0 + tx];
    __syncthreads();
#pragma unroll
    for (int i = 0; i < 4; i++)
        Wtl[(size_t)(n0 + ty + i * 8) * K + k0 + tx] = __float2half_rn(tile[tx][ty + i * 8]);
}

// ---------------- embedding ----------------
__global__ __launch_bounds__(256) void embed_kernel(const int* __restrict__ ids,
                                                    const float* __restrict__ emb,
                                                    float* __restrict__ out) {
    int m = blockIdx.x, t = threadIdx.x;
    int id = ids[m];
    ((float4*)(out + (size_t)m * Hx))[t] = ((const float4*)(emb + (size_t)id * Hx))[t];
}

// ---------------- layernorm ----------------
template<bool HALF_OUT>
__global__ __launch_bounds__(256) void ln_kernel(const float* __restrict__ x,
                                                 const float* __restrict__ g,
                                                 const float* __restrict__ b,
                                                 float* __restrict__ outf,
                                                 half* __restrict__ outh) {
    int m = blockIdx.x, t = threadIdx.x;
    __shared__ float red[8];
    float4 v = ((const float4*)(x + (size_t)m * Hx))[t];

    float s = v.x + v.y + v.z + v.w;
#pragma unroll
    for (int o = 16; o; o >>= 1) s += __shfl_xor_sync(0xffffffffu, s, o);
    if ((t & 31) == 0) red[t >> 5] = s;
    __syncthreads();
    float mu = 0.f;
#pragma unroll
    for (int w = 0; w < 8; w++) mu += red[w];
    mu *= (1.0f / Hx);
    __syncthreads();

    float d0 = v.x - mu, d1 = v.y - mu, d2 = v.z - mu, d3 = v.w - mu;
    float s2 = d0*d0 + d1*d1 + d2*d2 + d3*d3;
#pragma unroll
    for (int o = 16; o; o >>= 1) s2 += __shfl_xor_sync(0xffffffffu, s2, o);
    if ((t & 31) == 0) red[t >> 5] = s2;
    __syncthreads();
    float var = 0.f;
#pragma unroll
    for (int w = 0; w < 8; w++) var += red[w];
    var *= (1.0f / Hx);
    float inv = rsqrtf(var + 1e-5f);

    float4 gg = ((const float4*)g)[t];
    float4 bb = ((const float4*)b)[t];
    float o0 = d0 * inv * gg.x + bb.x;
    float o1 = d1 * inv * gg.y + bb.y;
    float o2 = d2 * inv * gg.z + bb.z;
    float o3 = d3 * inv * gg.w + bb.w;
    if (HALF_OUT) {
        *(half2*)(outh + (size_t)m * Hx + t * 4) = __floats2half2_rn(o0, o1);
        *(half2*)(outh + (size_t)m * Hx + t * 4 + 2) = __floats2half2_rn(o2, o3);
    } else {
        float4 o4; o4.x = o0; o4.y = o1; o4.z = o2; o4.w = o3;
        ((float4*)(outf + (size_t)m * Hx))[t] = o4;
    }
}

// ======= fp16 GEMM, 4-stage cp.async + ldmatrix ==============================
#define HST 40
#define NSTAGE 4
#define STG_HALVES (128 * HST)
#define GEMM_SMEM (NSTAGE * 2 * STG_HALVES * 2)   // 81920 B

template<bool GELU, bool RESID, bool OUT_HALF>
__global__ __launch_bounds__(256, 2) void gemm_h16(const half* __restrict__ A,
                                                   const half* __restrict__ Bw,
                                                   const float* __restrict__ bias,
                                                   const float* __restrict__ R,
                                                   float* __restrict__ C,
                                                   half* __restrict__ Ch,
                                                   int M, int N, int K) {
    extern __shared__ half smh[];
    const int t = threadIdx.x;
    const int warp = t >> 5, lane = t & 31;
    const int g = lane >> 2, q = lane & 3;
    const int wm = warp >> 1, wn = warp & 1;
    const int m0 = blockIdx.y * 128, n0 = blockIdx.x * 128;

    const int f_row = t >> 1, f_ch = (t & 1) * 16;
    const uint32_t smbase = (uint32_t)__cvta_generic_to_shared(smh);

    // ldmatrix per-lane offsets (halves, within a stage operand)
    // A: mats [m0-7,k][m8-15,k][m0-7,k+8][m8-15,k+8]
    const int a_off = (wm * 32 + (lane & 15)) * HST + (lane >> 4) * 8;
    // B: per pair p: mats [n0-7,k][n0-7,k+8][n8-15,k][n8-15,k+8]
    const int b_off = (wn * 64 + ((lane >> 4) * 8) + (lane & 7)) * HST + ((lane >> 3) & 1) * 8;

    float acc[2][8][4];
#pragma unroll
    for (int mt = 0; mt < 2; mt++)
#pragma unroll
        for (int nt = 0; nt < 8; nt++)
#pragma unroll
            for (int r = 0; r < 4; r++) acc[mt][nt][r] = 0.f;

    const half* Arow = A + (size_t)(m0 + f_row) * K + f_ch;
    const half* Brow = Bw + (size_t)(n0 + f_row) * K + f_ch;

#pragma unroll
    for (int s = 0; s < NSTAGE - 1; s++) {
        half* as = smh + s * 2 * STG_HALVES;
        half* bs = as + STG_HALVES;
        cp_async16(&as[f_row * HST + f_ch],     Arow + s * 32);
        cp_async16(&as[f_row * HST + f_ch + 8], Arow + s * 32 + 8);
        cp_async16(&bs[f_row * HST + f_ch],     Brow + s * 32);
        cp_async16(&bs[f_row * HST + f_ch + 8], Brow + s * 32 + 8);
        cp_commit();
    }

    const int T = K >> 5;
    for (int i = 0; i < T; i++) {
        const int s = i & (NSTAGE - 1);
        cp_wait2();
        __syncthreads();

        if (i + NSTAGE - 1 < T) {
            const int sn = (i + NSTAGE - 1) & (NSTAGE - 1);
            const int kn = (i + NSTAGE - 1) * 32;
            half* as = smh + sn * 2 * STG_HALVES;
            half* bs = as + STG_HALVES;
            cp_async16(&as[f_row * HST + f_ch],     Arow + kn);
            cp_async16(&as[f_row * HST + f_ch + 8], Arow + kn + 8);
            cp_async16(&bs[f_row * HST + f_ch],     Brow + kn);
            cp_async16(&bs[f_row * HST + f_ch + 8], Brow + kn + 8);
        }
        cp_commit();

        const uint32_t as_b = smbase + (uint32_t)(s * 2 * STG_HALVES) * 2;
        const uint32_t bs_b = as_b + (uint32_t)STG_HALVES * 2;
#pragma unroll
        for (int ks = 0; ks < 2; ks++) {
            const int k = ks * 16;
            uint32_t af[2][4], bf[8][2];
#pragma unroll
            for (int mt = 0; mt < 2; mt++)
                ldsm_x4(af[mt][0], af[mt][1], af[mt][2], af[mt][3],
                        as_b + (uint32_t)(a_off + mt * 16 * HST + k) * 2);
#pragma unroll
            for (int p = 0; p < 4; p++)
                ldsm_x4(bf[2*p][0], bf[2*p][1], bf[2*p+1][0], bf[2*p+1][1],
                        bs_b + (uint32_t)(b_off + p * 16 * HST + k) * 2);
#pragma unroll
            for (int mt = 0; mt < 2; mt++)
#pragma unroll
                for (int nt = 0; nt < 8; nt++)
                    mma_f16(acc[mt][nt], af[mt], bf[nt]);
        }
        // NOTE: no bottom __syncthreads — top sync of iter i+1 protects stage reuse
    }

    // ---- epilogue
#pragma unroll
    for (int mt = 0; mt < 2; mt++) {
#pragma unroll
        for (int nt = 0; nt < 8; nt++) {
            int r0 = m0 + wm * 32 + mt * 16 + g;
            int c0 = n0 + wn * 64 + nt * 8 + q * 2;
            float b0 = bias ? bias[c0] : 0.f;
            float b1 = bias ? bias[c0 + 1] : 0.f;
#pragma unroll
            for (int hf = 0; hf < 2; hf++) {
                int row = r0 + hf * 8;
                float v0 = acc[mt][nt][hf * 2 + 0] + b0;
                float v1 = acc[mt][nt][hf * 2 + 1] + b1;
                if (GELU) { v0 = gelu_f(v0); v1 = gelu_f(v1); }
                if (RESID) {
                    const float2 rr = *(const float2*)(R + (size_t)row * N + c0);
                    v0 += rr.x; v1 += rr.y;
                }
                if (OUT_HALF) {
                    *(half2*)(Ch + (size_t)row * N + c0) = __floats2half2_rn(v0, v1);
                } else {
                    float2 o2; o2.x = v0; o2.y = v1;
                    *(float2*)(C + (size_t)row * N + c0) = o2;
                }
            }
        }
    }
}

// ---------------- fused flash attention (unchanged) ----------------
#define ATTN_SMEM_FLOATS (64*68*3 + 64*72)

__global__ __launch_bounds__(128) void attn_kernel(const float* __restrict__ qkv,
                                                   const int* __restrict__ sp,
                                                   half* __restrict__ attn) {
    extern __shared__ float sm[];
    float* Qs = sm;
    float* Ks = Qs + 64 * 68;
    float* Vs = Ks + 64 * 68;
    float* Ps = Vs + 64 * 72;

    const int it = blockIdx.x, bn = blockIdx.y;
    const int b = bn >> 4, n = bn & 15;
    const int t = threadIdx.x, w = t >> 5, lane = t & 31;
    const int g = lane >> 2, q = lane & 3;
    const int i0 = it * 64;
    const int spv = sp[b];
    const float slope2 = exp2f(-0.5f * (float)(n + 1)) * LOG2E;
    const float qscale = 0.125f * LOG2E;

#pragma unroll
    for (int l = 0; l < 8; l++) {
        int e = t + l * 128;
        int row = e >> 4, d4 = (e & 15) * 4;
        float4 v = *(const float4*)(qkv + (size_t)(b * Sx + i0 + row) * 3072 + n * 64 + d4);
        v.x = to_tf32(v.x * qscale); v.y = to_tf32(v.y * qscale);
        v.z = to_tf32(v.z * qscale); v.w = to_tf32(v.w * qscale);
        *(float4*)&Qs[row * 68 + d4] = v;
    }

    float o[8][4];
#pragma unroll
    for (int nt = 0; nt < 8; nt++)
#pragma unroll
        for (int c = 0; c < 4; c++) o[nt][c] = 0.f;
    float m0 = -1e30f, m1 = -1e30f, l0 = 0.f, l1 = 0.f;

    const int r0 = w * 16 + g;
    const int rowA = i0 + r0, rowB = rowA + 8;

    for (int jt = 0; jt <= it; jt++) {
        const int j0 = jt * 64;
        __syncthreads();
#pragma unroll
        for (int l = 0; l < 8; l++) {
            int e = t + l * 128;
            int row = e >> 4, d4 = (e & 15) * 4;
            const float* base = qkv + (size_t)(b * Sx + j0 + row) * 3072 + n * 64 + d4;
            float4 kv = *(const float4*)(base + 1024);
            kv.x = to_tf32(kv.x); kv.y = to_tf32(kv.y);
            kv.z = to_tf32(kv.z); kv.w = to_tf32(kv.w);
            *(float4*)&Ks[row * 68 + d4] = kv;
            float4 vv = *(const float4*)(base + 2048);
            vv.x = to_tf32(vv.x); vv.y = to_tf32(vv.y);
            vv.z = to_tf32(vv.z); vv.w = to_tf32(vv.w);
            *(float4*)&Vs[row * 72 + d4] = vv;
        }
        __syncthreads();

        float s[8][4];
#pragma unroll
        for (int nt = 0; nt < 8; nt++)
#pragma unroll
            for (int c = 0; c < 4; c++) s[nt][c] = 0.f;
#pragma unroll
        for (int kk = 0; kk < 8; kk++) {
            const int k = kk * 8;
            uint32_t a[4];
            a[0] = __float_as_uint(Qs[(r0    ) * 68 + k + q]);
            a[1] = __float_as_uint(Qs[(r0 + 8) * 68 + k + q]);
            a[2] = __float_as_uint(Qs[(r0    ) * 68 + k + q + 4]);
            a[3] = __float_as_uint(Qs[(r0 + 8) * 68 + k + q + 4]);
#pragma unroll
            for (int nt = 0; nt < 8; nt++) {
                uint32_t bfr[2];
                bfr[0] = __float_as_uint(Ks[(nt * 8 + g) * 68 + k + q]);
                bfr[1] = __float_as_uint(Ks[(nt * 8 + g) * 68 + k + q + 4]);
                mma_tf32(s[nt], a, bfr);
            }
        }

#pragma unroll
        for (int nt = 0; nt < 8; nt++) {
#pragma unroll
            for (int c = 0; c < 4; c++) {
                int i = (c < 2) ? rowA : rowB;
                int j = j0 + nt * 8 + 2 * q + (c & 1);
                bool allowed = (j <= i) && !((i >= spv) && (j < spv));
                s[nt][c] = allowed ? (s[nt][c] - slope2 * (float)(i - j)) : -1e30f;
            }
        }

        float mx0 = -1e30f, mx1 = -1e30f;
#pragma unroll
        for (int nt = 0; nt < 8; nt++) {
            mx0 = fmaxf(mx0, fmaxf(s[nt][0], s[nt][1]));
            mx1 = fmaxf(mx1, fmaxf(s[nt][2], s[nt][3]));
        }
        mx0 = fmaxf(mx0, __shfl_xor_sync(0xffffffffu, mx0, 1));
        mx0 = fmaxf(mx0, __shfl_xor_sync(0xffffffffu, mx0, 2));
        mx1 = fmaxf(mx1, __shfl_xor_sync(0xffffffffu, mx1, 1));
        mx1 = fmaxf(mx1, __shfl_xor_sync(0xffffffffu, mx1, 2));
        float mn0 = fmaxf(m0, mx0), mn1 = fmaxf(m1, mx1);
        float al0 = ex2(m0 - mn0), al1 = ex2(m1 - mn1);

        float sum0 = 0.f, sum1 = 0.f;
#pragma unroll
        for (int nt = 0; nt < 8; nt++) {
            float p0 = ex2(s[nt][0] - mn0);
            float p1 = ex2(s[nt][1] - mn0);
            float p2 = ex2(s[nt][2] - mn1);
            float p3 = ex2(s[nt][3] - mn1);
            sum0 += p0 + p1; sum1 += p2 + p3;
            float2 lo2; lo2.x = to_tf32(p0); lo2.y = to_tf32(p1);
            *(float2*)&Ps[(r0    ) * 68 + nt * 8 + 2 * q] = lo2;
            float2 hi2; hi2.x = to_tf32(p2); hi2.y = to_tf32(p3);
            *(float2*)&Ps[(r0 + 8) * 68 + nt * 8 + 2 * q] = hi2;
        }
        sum0 += __shfl_xor_sync(0xffffffffu, sum0, 1);
        sum0 += __shfl_xor_sync(0xffffffffu, sum0, 2);
        sum1 += __shfl_xor_sync(0xffffffffu, sum1, 1);
        sum1 += __shfl_xor_sync(0xffffffffu, sum1, 2);
        l0 = l0 * al0 + sum0;
        l1 = l1 * al1 + sum1;
        m0 = mn0; m1 = mn1;
#pragma unroll
        for (int nt = 0; nt < 8; nt++) {
            o[nt][0] *= al0; o[nt][1] *= al0;
            o[nt][2] *= al1; o[nt][3] *= al1;
        }
        __syncwarp();

#pragma unroll
        for (int kk = 0; kk < 8; kk++) {
            const int k = kk * 8;
            uint32_t a[4];
            a[0] = __float_as_uint(Ps[(r0    ) * 68 + k + q]);
            a[1] = __float_as_uint(Ps[(r0 + 8) * 68 + k + q]);
            a[2] = __float_as_uint(Ps[(r0    ) * 68 + k + q + 4]);
            a[3] = __float_as_uint(Ps[(r0 + 8) * 68 + k + q + 4]);
#pragma unroll
            for (int nt = 0; nt < 8; nt++) {
                uint32_t bfr[2];
                bfr[0] = __float_as_uint(Vs[(k + q    ) * 72 + nt * 8 + g]);
                bfr[1] = __float_as_uint(Vs[(k + q + 4) * 72 + nt * 8 + g]);
                mma_tf32(o[nt], a, bfr);
            }
        }
    }

    const float inv0 = 1.0f / l0, inv1 = 1.0f / l1;
#pragma unroll
    for (int nt = 0; nt < 8; nt++) {
        *(half2*)(attn + (size_t)(b * Sx + rowA) * Hx + n * 64 + nt * 8 + 2 * q) =
            __floats2half2_rn(o[nt][0] * inv0, o[nt][1] * inv0);
        *(half2*)(attn + (size_t)(b * Sx + rowB) * Hx + n * 64 + nt * 8 + 2 * q) =
            __floats2half2_rn(o[nt][2] * inv1, o[nt][3] * inv1);
    }
}

// ---------------- 3xTF32 logits GEMM (unchanged) ----------------
__global__ __launch_bounds__(128) void gemm_logits(const float* __restrict__ A,
                                                   const float* __restrict__ Bm,
                                                   float* __restrict__ C,
                                                   int M, int N, int K) {
    __shared__ float Ah[64 * 36], Al[64 * 36];
    __shared__ float Bh[32 * 72], Bl[32 * 72];
    const int t = threadIdx.x;
    const int warp = t >> 5, lane = t & 31;
    const int g = lane >> 2, q = lane & 3;
    const int wm = warp >> 1, wn = warp & 1;
    const int m0 = blockIdx.y * 64, n0 = blockIdx.x * 64;

    float acc[2][4][4];
#pragma unroll
    for (int mt = 0; mt < 2; mt++)
#pragma unroll
        for (int nt = 0; nt < 4; nt++)
#pragma unroll
            for (int r = 0; r < 4; r++) acc[mt][nt][r] = 0.f;

    for (int k0 = 0; k0 < K; k0 += 32) {
        {
            int row = t >> 1, c4 = (t & 1) * 16;
#pragma unroll
            for (int p = 0; p < 4; p++) {
                float4 v = *(const float4*)(A + (size_t)(m0 + row) * K + k0 + c4 + p * 4);
                float4 hi, lo;
                hi.x = to_tf32(v.x); lo.x = to_tf32(v.x - hi.x);
                hi.y = to_tf32(v.y); lo.y = to_tf32(v.y - hi.y);
                hi.z = to_tf32(v.z); lo.z = to_tf32(v.z - hi.z);
                hi.w = to_tf32(v.w); lo.w = to_tf32(v.w - hi.w);
                *(float4*)&Ah[row * 36 + c4 + p * 4] = hi;
                *(float4*)&Al[row * 36 + c4 + p * 4] = lo;
            }
        }
        {
#pragma unroll
            for (int p = 0; p < 4; p++) {
                int e = t + p * 128;
                int row = e & 63, c4 = (e >> 6) * 4;
                float4 v = *(const float4*)(Bm + (size_t)(n0 + row) * K + k0 + c4);
                float hv, lv;
                hv = to_tf32(v.x); lv = to_tf32(v.x - hv);
                Bh[(c4 + 0) * 72 + row] = hv; Bl[(c4 + 0) * 72 + row] = lv;
                hv = to_tf32(v.y); lv = to_tf32(v.y - hv);
                Bh[(c4 + 1) * 72 + row] = hv; Bl[(c4 + 1) * 72 + row] = lv;
                hv = to_tf32(v.z); lv = to_tf32(v.z - hv);
                Bh[(c4 + 2) * 72 + row] = hv; Bl[(c4 + 2) * 72 + row] = lv;
                hv = to_tf32(v.w); lv = to_tf32(v.w - hv);
                Bh[(c4 + 3) * 72 + row] = hv; Bl[(c4 + 3) * 72 + row] = lv;
            }
        }
        __syncthreads();

#pragma unroll
        for (int ks = 0; ks < 4; ks++) {
            const int k = ks * 8;
            uint32_t ah[2][4], al[2][4], bh[4][2], bl[4][2];
#pragma unroll
            for (int mt = 0; mt < 2; mt++) {
                int r = wm * 32 + mt * 16 + g;
                ah[mt][0] = __float_as_uint(Ah[(r    ) * 36 + k + q]);
                ah[mt][1] = __float_as_uint(Ah[(r + 8) * 36 + k + q]);
                ah[mt][2] = __float_as_uint(Ah[(r    ) * 36 + k + q + 4]);
                ah[mt][3] = __float_as_uint(Ah[(r + 8) * 36 + k + q + 4]);
                al[mt][0] = __float_as_uint(Al[(r    ) * 36 + k + q]);
                al[mt][1] = __float_as_uint(Al[(r + 8) * 36 + k + q]);
                al[mt][2] = __float_as_uint(Al[(r    ) * 36 + k + q + 4]);
                al[mt][3] = __float_as_uint(Al[(r + 8) * 36 + k + q + 4]);
            }
#pragma unroll
            for (int nt = 0; nt < 4; nt++) {
                int nn = wn * 32 + nt * 8 + g;
                bh[nt][0] = __float_as_uint(Bh[(k + q    ) * 72 + nn]);
                bh[nt][1] = __float_as_uint(Bh[(k + q + 4) * 72 + nn]);
                bl[nt][0] = __float_as_uint(Bl[(k + q    ) * 72 + nn]);
                bl[nt][1] = __float_as_uint(Bl[(k + q + 4) * 72 + nn]);
            }
#pragma unroll
            for (int mt = 0; mt < 2; mt++)
#pragma unroll
                for (int nt = 0; nt < 4; nt++) {
                    mma_tf32(acc[mt][nt], ah[mt], bl[nt]);
                    mma_tf32(acc[mt][nt], al[mt], bh[nt]);
                    mma_tf32(acc[mt][nt], ah[mt], bh[nt]);
                }
        }
        __syncthreads();
    }

#pragma unroll
    for (int mt = 0; mt < 2; mt++) {
#pragma unroll
        for (int nt = 0; nt < 4; nt++) {
            int r0 = m0 + wm * 32 + mt * 16 + g;
            int c0 = n0 + wn * 32 + nt * 8 + q * 2;
#pragma unroll
            for (int hf = 0; hf < 2; hf++) {
                int row = r0 + hf * 8;
                float2 o2;
                o2.x = acc[mt][nt][hf * 2 + 0];
                o2.y = acc[mt][nt][hf * 2 + 1];
                *(float2*)(C + (size_t)row * N + c0) = o2;
            }
        }
    }
}

// ---------------- launcher ----------------
extern "C" void kernel_launch(void* const* d_in, const int* in_sizes, int n_in,
                              void* d_out, int out_size) {
    const int*   ids    = (const int*)d_in[0];
    const int*   sp     = (const int*)d_in[1];
    const float* emb    = (const float*)d_in[2];
    const float* ln1_g  = (const float*)d_in[3];
    const float* ln1_b  = (const float*)d_in[4];
    const float* Wqkv   = (const float*)d_in[5];
    const float* bqkv   = (const float*)d_in[6];
    const float* Wo     = (const float*)d_in[7];
    const float* bo     = (const float*)d_in[8];
    const float* ln2_g  = (const float*)d_in[9];
    const float* ln2_b  = (const float*)d_in[10];
    const float* Wfc    = (const float*)d_in[11];
    const float* bfc    = (const float*)d_in[12];
    const float* Wproj  = (const float*)d_in[13];
    const float* bproj  = (const float*)d_in[14];
    const float* lnf_g  = (const float*)d_in[15];
    const float* lnf_b  = (const float*)d_in[16];
    float* out = (float*)d_out;

    float *x, *h, *qkv;
    half *hh, *attn_h, *mid_h, *wqkv_t, *wo_t, *wfc_t, *wproj_t;
    cudaGetSymbolAddress((void**)&x,       g_x);
    cudaGetSymbolAddress((void**)&h,       g_h);
    cudaGetSymbolAddress((void**)&qkv,     g_qkv);
    cudaGetSymbolAddress((void**)&hh,      g_hh);
    cudaGetSymbolAddress((void**)&attn_h,  g_attn_h);
    cudaGetSymbolAddress((void**)&mid_h,   g_mid_h);
    cudaGetSymbolAddress((void**)&wqkv_t,  g_Wqkv_t);
    cudaGetSymbolAddress((void**)&wo_t,    g_Wo_t);
    cudaGetSymbolAddress((void**)&wfc_t,   g_Wfc_t);
    cudaGetSymbolAddress((void**)&wproj_t, g_Wproj_t);

    const int attn_smem = ATTN_SMEM_FLOATS * 4;
    cudaFuncSetAttribute(attn_kernel, cudaFuncAttributeMaxDynamicSharedMemorySize, attn_smem);
    cudaFuncSetAttribute(gemm_h16<false, false, false>, cudaFuncAttributeMaxDynamicSharedMemorySize, GEMM_SMEM);
    cudaFuncSetAttribute(gemm_h16<false, true, false>,  cudaFuncAttributeMaxDynamicSharedMemorySize, GEMM_SMEM);
    cudaFuncSetAttribute(gemm_h16<true, false, true>,   cudaFuncAttributeMaxDynamicSharedMemorySize, GEMM_SMEM);

    wtrans_kernel<<<dim3(3 * Hx / 32, Hx / 32, NLx), 256>>>(Wqkv, wqkv_t, Hx, 3 * Hx);
    wtrans_kernel<<<dim3(Hx / 32, Hx / 32, NLx), 256>>>(Wo, wo_t, Hx, Hx);
    wtrans_kernel<<<dim3(Fx / 32, Hx / 32, NLx), 256>>>(Wfc, wfc_t, Hx, Fx);
    wtrans_kernel<<<dim3(Hx / 32, Fx / 32, NLx), 256>>>(Wproj, wproj_t, Fx, Hx);

    embed_kernel<<<Mx, 256>>>(ids, emb, x);

    for (int l = 0; l < NLx; l++) {
        ln_kernel<true><<<Mx, 256>>>(x, ln1_g + l * Hx, ln1_b + l * Hx, nullptr, hh);
        gemm_h16<false, false, false><<<dim3(3 * Hx / 128, Mx / 128), 256, GEMM_SMEM>>>(
            hh, wqkv_t + (size_t)l * 3 * Hx * Hx, bqkv + (size_t)l * 3 * Hx, nullptr,
            qkv, nullptr, Mx, 3 * Hx, Hx);
        attn_kernel<<<dim3(Sx / 64, Bx * NHx), 128, attn_smem>>>(qkv, sp, attn_h);
        gemm_h16<false, true, false><<<dim3(Hx / 128, Mx / 128), 256, GEMM_SMEM>>>(
            attn_h, wo_t + (size_t)l * Hx * Hx, bo + (size_t)l * Hx, x,
            x, nullptr, Mx, Hx, Hx);
        ln_kernel<true><<<Mx, 256>>>(x, ln2_g + l * Hx, ln2_b + l * Hx, nullptr, hh);
        gemm_h16<true, false, true><<<dim3(Fx / 128, Mx / 128), 256, GEMM_SMEM>>>(
            hh, wfc_t + (size_t)l * Fx * Hx, bfc + (size_t)l * Fx, nullptr,
            nullptr, mid_h, Mx, Fx, Hx);
        gemm_h16<false, true, false><<<dim3(Hx / 128, Mx / 128), 256, GEMM_SMEM>>>(
            mid_h, wproj_t + (size_t)l * Hx * Fx, bproj + (size_t)l * Hx, x,
            x, nullptr, Mx, Hx, Fx);
    }

    ln_kernel<false><<<Mx, 256>>>(x, lnf_g, lnf_b, h, nullptr);
    gemm_logits<<<dim3(Vx / 64, Mx / 64), 128>>>(h, emb, out, Mx, Vx, Hx);
}

// round 9
// speedup vs baseline: 1.9709x; 1.0568x over previous
#include <cuda_runtime.h>
#include <cuda_fp16.h>
#include <math.h>
#include <stdint.h>

#define Bx  16
#define Sx  512
#define Vx  512
#define Hx  1024
#define NLx 8
#define NHx 16
#define DHx 64
#define Fx  4096
#define Mx  (Bx*Sx)

#define LOG2E 1.4426950408889634f

// ---------------- scratch ----------------
__device__ float g_x[Mx*Hx];
__device__ float g_h[Mx*Hx];
__device__ float g_qkv[Mx*3*Hx];
__device__ half  g_hh[Mx*Hx];
__device__ half  g_attn_h[Mx*Hx];
__device__ half  g_mid_h[(size_t)Mx*Fx];
__device__ half  g_Wqkv_t[(size_t)NLx*3*Hx*Hx];
__device__ half  g_Wo_t[(size_t)NLx*Hx*Hx];
__device__ half  g_Wfc_t[(size_t)NLx*Fx*Hx];
__device__ half  g_Wproj_t[(size_t)NLx*Hx*Fx];

// ---------------- helpers ----------------
__device__ __forceinline__ float to_tf32(float x) {
    float r;
    asm("cvt.rna.tf32.f32 %0, %1;" : "=f"(r) : "f"(x));
    return r;
}
__device__ __forceinline__ float ex2(float x) {
    float r;
    asm("ex2.approx.f32 %0, %1;" : "=f"(r) : "f"(x));
    return r;
}
__device__ __forceinline__ void mma_tf32(float* c, const uint32_t* a, const uint32_t* b) {
    asm volatile(
        "mma.sync.aligned.m16n8k8.row.col.f32.tf32.tf32.f32 "
        "{%0,%1,%2,%3}, {%4,%5,%6,%7}, {%8,%9}, {%0,%1,%2,%3};\n"
        : "+f"(c[0]), "+f"(c[1]), "+f"(c[2]), "+f"(c[3])
        : "r"(a[0]), "r"(a[1]), "r"(a[2]), "r"(a[3]), "r"(b[0]), "r"(b[1]));
}
__device__ __forceinline__ void mma_f16(float* c, const uint32_t* a, const uint32_t* b) {
    asm volatile(
        "mma.sync.aligned.m16n8k16.row.col.f32.f16.f16.f32 "
        "{%0,%1,%2,%3}, {%4,%5,%6,%7}, {%8,%9}, {%0,%1,%2,%3};\n"
        : "+f"(c[0]), "+f"(c[1]), "+f"(c[2]), "+f"(c[3])
        : "r"(a[0]), "r"(a[1]), "r"(a[2]), "r"(a[3]), "r"(b[0]), "r"(b[1]));
}
__device__ __forceinline__ void ldsm_x4(uint32_t& r0, uint32_t& r1, uint32_t& r2, uint32_t& r3,
                                        uint32_t addr) {
    asm volatile("ldmatrix.sync.aligned.m8n8.x4.shared.b16 {%0,%1,%2,%3}, [%4];"
                 : "=r"(r0), "=r"(r1), "=r"(r2), "=r"(r3) : "r"(addr));
}
__device__ __forceinline__ void ldsm_x4_t(uint32_t& r0, uint32_t& r1, uint32_t& r2, uint32_t& r3,
                                          uint32_t addr) {
    asm volatile("ldmatrix.sync.aligned.m8n8.x4.trans.shared.b16 {%0,%1,%2,%3}, [%4];"
                 : "=r"(r0), "=r"(r1), "=r"(r2), "=r"(r3) : "r"(addr));
}
__device__ __forceinline__ void cp_async16(void* smem_dst, const void* gmem_src) {
    uint32_t s = (uint32_t)__cvta_generic_to_shared(smem_dst);
    asm volatile("cp.async.cg.shared.global [%0], [%1], 16;\n" :: "r"(s), "l"(gmem_src));
}
__device__ __forceinline__ void cp_commit() { asm volatile("cp.async.commit_group;\n"); }
__device__ __forceinline__ void cp_wait2() { asm volatile("cp.async.wait_group 2;\n"); }
__device__ __forceinline__ float gelu_f(float v) {
    return 0.5f * v * (1.0f + tanhf(0.7978845608028654f * (v + 0.044715f * v * v * v)));
}

// ---------------- weight transpose+convert ----------------
__global__ __launch_bounds__(256) void wtrans_kernel(const float* __restrict__ W,
                                                     half* __restrict__ Wt,
                                                     int K, int N) {
    __shared__ float tile[32][33];
    const size_t lsz = (size_t)K * N;
    const float* Wl = W + blockIdx.z * lsz;
    half* Wtl = Wt + blockIdx.z * lsz;
    int n0 = blockIdx.x * 32, k0 = blockIdx.y * 32;
    int tx = threadIdx.x & 31, ty = threadIdx.x >> 5;
#pragma unroll
    for (int i = 0; i < 4; i++)
        tile[ty + i * 8][tx] = Wl[(size_t)(k0 + ty + i * 8) * N + n0 + tx];
    __syncthreads();
#pragma unroll
    for (int i = 0; i < 4; i++)
        Wtl[(size_t)(n0 + ty + i * 8) * K + k0 + tx] = __float2half_rn(tile[tx][ty + i * 8]);
}

// ---------------- embedding ----------------
__global__ __launch_bounds__(256) void embed_kernel(const int* __restrict__ ids,
                                                    const float* __restrict__ emb,
                                                    float* __restrict__ out) {
    int m = blockIdx.x, t = threadIdx.x;
    int id = ids[m];
    ((float4*)(out + (size_t)m * Hx))[t] = ((const float4*)(emb + (size_t)id * Hx))[t];
}

// ---------------- layernorm: warp-per-row, 8 rows/block ---------------------
template<bool HALF_OUT>
__global__ __launch_bounds__(256) void ln_kernel(const float* __restrict__ x,
                                                 const float* __restrict__ g,
                                                 const float* __restrict__ b,
                                                 float* __restrict__ outf,
                                                 half* __restrict__ outh) {
    const int lane = threadIdx.x & 31;
    const int m = blockIdx.x * 8 + (threadIdx.x >> 5);
    const float4* xr = (const float4*)(x + (size_t)m * Hx);

    float4 v[8];
    float s = 0.f;
#pragma unroll
    for (int i = 0; i < 8; i++) {
        v[i] = xr[lane + i * 32];
        s += v[i].x + v[i].y + v[i].z + v[i].w;
    }
#pragma unroll
    for (int o = 16; o; o >>= 1) s += __shfl_xor_sync(0xffffffffu, s, o);
    float mu = s * (1.0f / Hx);

    float s2 = 0.f;
#pragma unroll
    for (int i = 0; i < 8; i++) {
        float d0 = v[i].x - mu, d1 = v[i].y - mu, d2 = v[i].z - mu, d3 = v[i].w - mu;
        s2 += d0*d0 + d1*d1 + d2*d2 + d3*d3;
    }
#pragma unroll
    for (int o = 16; o; o >>= 1) s2 += __shfl_xor_sync(0xffffffffu, s2, o);
    float inv = rsqrtf(s2 * (1.0f / Hx) + 1e-5f);

#pragma unroll
    for (int i = 0; i < 8; i++) {
        float4 gg = ((const float4*)g)[lane + i * 32];
        float4 bb = ((const float4*)b)[lane + i * 32];
        float o0 = (v[i].x - mu) * inv * gg.x + bb.x;
        float o1 = (v[i].y - mu) * inv * gg.y + bb.y;
        float o2 = (v[i].z - mu) * inv * gg.z + bb.z;
        float o3 = (v[i].w - mu) * inv * gg.w + bb.w;
        if (HALF_OUT) {
            int c = (lane + i * 32) * 4;
            *(half2*)(outh + (size_t)m * Hx + c) = __floats2half2_rn(o0, o1);
            *(half2*)(outh + (size_t)m * Hx + c + 2) = __floats2half2_rn(o2, o3);
        } else {
            float4 o4; o4.x = o0; o4.y = o1; o4.z = o2; o4.w = o3;
            ((float4*)(outf + (size_t)m * Hx))[lane + i * 32] = o4;
        }
    }
}

// ======= fp16 GEMM, 4-stage cp.async + ldmatrix (unchanged from R8) =========
#define HST 40
#define NSTAGE 4
#define STG_HALVES (128 * HST)
#define GEMM_SMEM (NSTAGE * 2 * STG_HALVES * 2)

template<bool GELU, bool RESID, bool OUT_HALF>
__global__ __launch_bounds__(256, 2) void gemm_h16(const half* __restrict__ A,
                                                   const half* __restrict__ Bw,
                                                   const float* __restrict__ bias,
                                                   const float* __restrict__ R,
                                                   float* __restrict__ C,
                                                   half* __restrict__ Ch,
                                                   int M, int N, int K) {
    extern __shared__ half smh[];
    const int t = threadIdx.x;
    const int warp = t >> 5, lane = t & 31;
    const int g = lane >> 2, q = lane & 3;
    const int wm = warp >> 1, wn = warp & 1;
    const int m0 = blockIdx.y * 128, n0 = blockIdx.x * 128;

    const int f_row = t >> 1, f_ch = (t & 1) * 16;
    const uint32_t smbase = (uint32_t)__cvta_generic_to_shared(smh);

    const int a_off = (wm * 32 + (lane & 15)) * HST + (lane >> 4) * 8;
    const int b_off = (wn * 64 + ((lane >> 4) * 8) + (lane & 7)) * HST + ((lane >> 3) & 1) * 8;

    float acc[2][8][4];
#pragma unroll
    for (int mt = 0; mt < 2; mt++)
#pragma unroll
        for (int nt = 0; nt < 8; nt++)
#pragma unroll
            for (int r = 0; r < 4; r++) acc[mt][nt][r] = 0.f;

    const half* Arow = A + (size_t)(m0 + f_row) * K + f_ch;
    const half* Brow = Bw + (size_t)(n0 + f_row) * K + f_ch;

#pragma unroll
    for (int s = 0; s < NSTAGE - 1; s++) {
        half* as = smh + s * 2 * STG_HALVES;
        half* bs = as + STG_HALVES;
        cp_async16(&as[f_row * HST + f_ch],     Arow + s * 32);
        cp_async16(&as[f_row * HST + f_ch + 8], Arow + s * 32 + 8);
        cp_async16(&bs[f_row * HST + f_ch],     Brow + s * 32);
        cp_async16(&bs[f_row * HST + f_ch + 8], Brow + s * 32 + 8);
        cp_commit();
    }

    const int T = K >> 5;
    for (int i = 0; i < T; i++) {
        const int s = i & (NSTAGE - 1);
        cp_wait2();
        __syncthreads();

        if (i + NSTAGE - 1 < T) {
            const int sn = (i + NSTAGE - 1) & (NSTAGE - 1);
            const int kn = (i + NSTAGE - 1) * 32;
            half* as = smh + sn * 2 * STG_HALVES;
            half* bs = as + STG_HALVES;
            cp_async16(&as[f_row * HST + f_ch],     Arow + kn);
            cp_async16(&as[f_row * HST + f_ch + 8], Arow + kn + 8);
            cp_async16(&bs[f_row * HST + f_ch],     Brow + kn);
            cp_async16(&bs[f_row * HST + f_ch + 8], Brow + kn + 8);
        }
        cp_commit();

        const uint32_t as_b = smbase + (uint32_t)(s * 2 * STG_HALVES) * 2;
        const uint32_t bs_b = as_b + (uint32_t)STG_HALVES * 2;
#pragma unroll
        for (int ks = 0; ks < 2; ks++) {
            const int k = ks * 16;
            uint32_t af[2][4], bf[8][2];
#pragma unroll
            for (int mt = 0; mt < 2; mt++)
                ldsm_x4(af[mt][0], af[mt][1], af[mt][2], af[mt][3],
                        as_b + (uint32_t)(a_off + mt * 16 * HST + k) * 2);
#pragma unroll
            for (int p = 0; p < 4; p++)
                ldsm_x4(bf[2*p][0], bf[2*p][1], bf[2*p+1][0], bf[2*p+1][1],
                        bs_b + (uint32_t)(b_off + p * 16 * HST + k) * 2);
#pragma unroll
            for (int mt = 0; mt < 2; mt++)
#pragma unroll
                for (int nt = 0; nt < 8; nt++)
                    mma_f16(acc[mt][nt], af[mt], bf[nt]);
        }
    }

#pragma unroll
    for (int mt = 0; mt < 2; mt++) {
#pragma unroll
        for (int nt = 0; nt < 8; nt++) {
            int r0 = m0 + wm * 32 + mt * 16 + g;
            int c0 = n0 + wn * 64 + nt * 8 + q * 2;
            float b0 = bias ? bias[c0] : 0.f;
            float b1 = bias ? bias[c0 + 1] : 0.f;
#pragma unroll
            for (int hf = 0; hf < 2; hf++) {
                int row = r0 + hf * 8;
                float v0 = acc[mt][nt][hf * 2 + 0] + b0;
                float v1 = acc[mt][nt][hf * 2 + 1] + b1;
                if (GELU) { v0 = gelu_f(v0); v1 = gelu_f(v1); }
                if (RESID) {
                    const float2 rr = *(const float2*)(R + (size_t)row * N + c0);
                    v0 += rr.x; v1 += rr.y;
                }
                if (OUT_HALF) {
                    *(half2*)(Ch + (size_t)row * N + c0) = __floats2half2_rn(v0, v1);
                } else {
                    float2 o2; o2.x = v0; o2.y = v1;
                    *(float2*)(C + (size_t)row * N + c0) = o2;
                }
            }
        }
    }
}

// ---------------- fused flash attention: fp16 HMMA ---------------------------
// Q/K/V/P half, stride-72 rows (144B = 9x16B: aligned, ldmatrix bank-free).
// QK^T: A=Qs[i][d] (x4), B=Ks[j][d] n-major (x4, GEMM pattern).
// PV:   A=Ps[i][j] (x4), B=Vs[j][d] k-major row-major via x4.trans.
#define AHS 72
#define ATTN_SMEM_BYTES (4 * 64 * AHS * 2)   // 36864

__global__ __launch_bounds__(128) void attn_kernel(const float* __restrict__ qkv,
                                                   const int* __restrict__ sp,
                                                   half* __restrict__ attn) {
    extern __shared__ half smah[];
    half* Qs = smah;
    half* Ks = Qs + 64 * AHS;
    half* Vs = Ks + 64 * AHS;
    half* Ps = Vs + 64 * AHS;
    const uint32_t qs_b = (uint32_t)__cvta_generic_to_shared(Qs);
    const uint32_t ks_b = (uint32_t)__cvta_generic_to_shared(Ks);
    const uint32_t vs_b = (uint32_t)__cvta_generic_to_shared(Vs);
    const uint32_t ps_b = (uint32_t)__cvta_generic_to_shared(Ps);

    const int it = blockIdx.x, bn = blockIdx.y;
    const int b = bn >> 4, n = bn & 15;
    const int t = threadIdx.x, w = t >> 5, lane = t & 31;
    const int g = lane >> 2, q = lane & 3;
    const int i0 = it * 64;
    const int spv = sp[b];
    const float slope2 = exp2f(-0.5f * (float)(n + 1)) * LOG2E;
    const float qscale = 0.125f * LOG2E;

    // ---- fill Q (scaled, half)
#pragma unroll
    for (int l = 0; l < 4; l++) {
        int e = t + l * 128;
        int row = e >> 3, c8 = (e & 7) * 8;
        const float* src = qkv + (size_t)(b * Sx + i0 + row) * 3072 + n * 64 + c8;
        float4 f0 = *(const float4*)src;
        float4 f1 = *(const float4*)(src + 4);
        half2 h[4];
        h[0] = __floats2half2_rn(f0.x * qscale, f0.y * qscale);
        h[1] = __floats2half2_rn(f0.z * qscale, f0.w * qscale);
        h[2] = __floats2half2_rn(f1.x * qscale, f1.y * qscale);
        h[3] = __floats2half2_rn(f1.z * qscale, f1.w * qscale);
        *(uint4*)&Qs[row * AHS + c8] = *(uint4*)h;
    }
    __syncthreads();

    // ---- Q fragments (hoisted: reused for all key tiles)
    const int r0 = w * 16 + g;
    const int a_off = (w * 16 + (lane & 15)) * AHS + (lane >> 4) * 8;
    uint32_t qf[4][4];
#pragma unroll
    for (int kk = 0; kk < 4; kk++)
        ldsm_x4(qf[kk][0], qf[kk][1], qf[kk][2], qf[kk][3],
                qs_b + (uint32_t)(a_off + kk * 16) * 2);

    // B-frag offsets
    const int bk_off = (((lane >> 4) * 8) + (lane & 7)) * AHS + ((lane >> 3) & 1) * 8;  // QK (n-major)
    const int vt_off = (((lane >> 3) & 1) * 8 + (lane & 7)) * AHS + (lane >> 4) * 8;    // PV (trans)

    float o[8][4];
#pragma unroll
    for (int nt = 0; nt < 8; nt++)
#pragma unroll
        for (int c = 0; c < 4; c++) o[nt][c] = 0.f;
    float m0 = -1e30f, m1 = -1e30f, l0 = 0.f, l1 = 0.f;

    const int rowA = i0 + r0, rowB = rowA + 8;

    for (int jt = 0; jt <= it; jt++) {
        const int j0 = jt * 64;
        __syncthreads();
#pragma unroll
        for (int l = 0; l < 4; l++) {
            int e = t + l * 128;
            int row = e >> 3, c8 = (e & 7) * 8;
            const float* base = qkv + (size_t)(b * Sx + j0 + row) * 3072 + n * 64 + c8;
            float4 f0 = *(const float4*)(base + 1024);
            float4 f1 = *(const float4*)(base + 1028);
            half2 hk[4];
            hk[0] = __floats2half2_rn(f0.x, f0.y);
            hk[1] = __floats2half2_rn(f0.z, f0.w);
            hk[2] = __floats2half2_rn(f1.x, f1.y);
            hk[3] = __floats2half2_rn(f1.z, f1.w);
            *(uint4*)&Ks[row * AHS + c8] = *(uint4*)hk;
            float4 v0 = *(const float4*)(base + 2048);
            float4 v1 = *(const float4*)(base + 2052);
            half2 hv[4];
            hv[0] = __floats2half2_rn(v0.x, v0.y);
            hv[1] = __floats2half2_rn(v0.z, v0.w);
            hv[2] = __floats2half2_rn(v1.x, v1.y);
            hv[3] = __floats2half2_rn(v1.z, v1.w);
            *(uint4*)&Vs[row * AHS + c8] = *(uint4*)hv;
        }
        __syncthreads();

        // ---- QK^T
        float s[8][4];
#pragma unroll
        for (int nt = 0; nt < 8; nt++)
#pragma unroll
            for (int c = 0; c < 4; c++) s[nt][c] = 0.f;
#pragma unroll
        for (int kk = 0; kk < 4; kk++) {
            uint32_t bf[8][2];
#pragma unroll
            for (int p = 0; p < 4; p++)
                ldsm_x4(bf[2*p][0], bf[2*p][1], bf[2*p+1][0], bf[2*p+1][1],
                        ks_b + (uint32_t)(bk_off + p * 16 * AHS + kk * 16) * 2);
#pragma unroll
            for (int nt = 0; nt < 8; nt++)
                mma_f16(s[nt], qf[kk], bf[nt]);
        }

        // ---- bias + mask (log2 domain)
#pragma unroll
        for (int nt = 0; nt < 8; nt++) {
#pragma unroll
            for (int c = 0; c < 4; c++) {
                int i = (c < 2) ? rowA : rowB;
                int j = j0 + nt * 8 + 2 * q + (c & 1);
                bool allowed = (j <= i) && !((i >= spv) && (j < spv));
                s[nt][c] = allowed ? (s[nt][c] - slope2 * (float)(i - j)) : -1e30f;
            }
        }

        // ---- online softmax
        float mx0 = -1e30f, mx1 = -1e30f;
#pragma unroll
        for (int nt = 0; nt < 8; nt++) {
            mx0 = fmaxf(mx0, fmaxf(s[nt][0], s[nt][1]));
            mx1 = fmaxf(mx1, fmaxf(s[nt][2], s[nt][3]));
        }
        mx0 = fmaxf(mx0, __shfl_xor_sync(0xffffffffu, mx0, 1));
        mx0 = fmaxf(mx0, __shfl_xor_sync(0xffffffffu, mx0, 2));
        mx1 = fmaxf(mx1, __shfl_xor_sync(0xffffffffu, mx1, 1));
        mx1 = fmaxf(mx1, __shfl_xor_sync(0xffffffffu, mx1, 2));
        float mn0 = fmaxf(m0, mx0), mn1 = fmaxf(m1, mx1);
        float al0 = ex2(m0 - mn0), al1 = ex2(m1 - mn1);

        float sum0 = 0.f, sum1 = 0.f;
#pragma unroll
        for (int nt = 0; nt < 8; nt++) {
            float p0 = ex2(s[nt][0] - mn0);
            float p1 = ex2(s[nt][1] - mn0);
            float p2 = ex2(s[nt][2] - mn1);
            float p3 = ex2(s[nt][3] - mn1);
            sum0 += p0 + p1; sum1 += p2 + p3;
            *(half2*)&Ps[(r0    ) * AHS + nt * 8 + 2 * q] = __floats2half2_rn(p0, p1);
            *(half2*)&Ps[(r0 + 8) * AHS + nt * 8 + 2 * q] = __floats2half2_rn(p2, p3);
        }
        sum0 += __shfl_xor_sync(0xffffffffu, sum0, 1);
        sum0 += __shfl_xor_sync(0xffffffffu, sum0, 2);
        sum1 += __shfl_xor_sync(0xffffffffu, sum1, 1);
        sum1 += __shfl_xor_sync(0xffffffffu, sum1, 2);
        l0 = l0 * al0 + sum0;
        l1 = l1 * al1 + sum1;
        m0 = mn0; m1 = mn1;
#pragma unroll
        for (int nt = 0; nt < 8; nt++) {
            o[nt][0] *= al0; o[nt][1] *= al0;
            o[nt][2] *= al1; o[nt][3] *= al1;
        }
        __syncwarp();

        // ---- P @ V  (A from Ps, B from Vs via trans ldmatrix)
#pragma unroll
        for (int kk = 0; kk < 4; kk++) {
            uint32_t pf[4];
            ldsm_x4(pf[0], pf[1], pf[2], pf[3],
                    ps_b + (uint32_t)(a_off + kk * 16) * 2);
            uint32_t bf[8][2];
#pragma unroll
            for (int p = 0; p < 4; p++)
                ldsm_x4_t(bf[2*p][0], bf[2*p][1], bf[2*p+1][0], bf[2*p+1][1],
                          vs_b + (uint32_t)(vt_off + kk * 16 * AHS + p * 16) * 2);
#pragma unroll
            for (int nt = 0; nt < 8; nt++)
                mma_f16(o[nt], pf, bf[nt]);
        }
    }

    const float inv0 = 1.0f / l0, inv1 = 1.0f / l1;
#pragma unroll
    for (int nt = 0; nt < 8; nt++) {
        *(half2*)(attn + (size_t)(b * Sx + rowA) * Hx + n * 64 + nt * 8 + 2 * q) =
            __floats2half2_rn(o[nt][0] * inv0, o[nt][1] * inv0);
        *(half2*)(attn + (size_t)(b * Sx + rowB) * Hx + n * 64 + nt * 8 + 2 * q) =
            __floats2half2_rn(o[nt][2] * inv1, o[nt][3] * inv1);
    }
}

// ---------------- 3xTF32 logits GEMM (unchanged) ----------------
__global__ __launch_bounds__(128) void gemm_logits(const float* __restrict__ A,
                                                   const float* __restrict__ Bm,
                                                   float* __restrict__ C,
                                                   int M, int N, int K) {
    __shared__ float Ah[64 * 36], Al[64 * 36];
    __shared__ float Bh[32 * 72], Bl[32 * 72];
    const int t = threadIdx.x;
    const int warp = t >> 5, lane = t & 31;
    const int g = lane >> 2, q = lane & 3;
    const int wm = warp >> 1, wn = warp & 1;
    const int m0 = blockIdx.y * 64, n0 = blockIdx.x * 64;

    float acc[2][4][4];
#pragma unroll
    for (int mt = 0; mt < 2; mt++)
#pragma unroll
        for (int nt = 0; nt < 4; nt++)
#pragma unroll
            for (int r = 0; r < 4; r++) acc[mt][nt][r] = 0.f;

    for (int k0 = 0; k0 < K; k0 += 32) {
        {
            int row = t >> 1, c4 = (t & 1) * 16;
#pragma unroll
            for (int p = 0; p < 4; p++) {
                float4 v = *(const float4*)(A + (size_t)(m0 + row) * K + k0 + c4 + p * 4);
                float4 hi, lo;
                hi.x = to_tf32(v.x); lo.x = to_tf32(v.x - hi.x);
                hi.y = to_tf32(v.y); lo.y = to_tf32(v.y - hi.y);
                hi.z = to_tf32(v.z); lo.z = to_tf32(v.z - hi.z);
                hi.w = to_tf32(v.w); lo.w = to_tf32(v.w - hi.w);
                *(float4*)&Ah[row * 36 + c4 + p * 4] = hi;
                *(float4*)&Al[row * 36 + c4 + p * 4] = lo;
            }
        }
        {
#pragma unroll
            for (int p = 0; p < 4; p++) {
                int e = t + p * 128;
                int row = e & 63, c4 = (e >> 6) * 4;
                float4 v = *(const float4*)(Bm + (size_t)(n0 + row) * K + k0 + c4);
                float hv, lv;
                hv = to_tf32(v.x); lv = to_tf32(v.x - hv);
                Bh[(c4 + 0) * 72 + row] = hv; Bl[(c4 + 0) * 72 + row] = lv;
                hv = to_tf32(v.y); lv = to_tf32(v.y - hv);
                Bh[(c4 + 1) * 72 + row] = hv; Bl[(c4 + 1) * 72 + row] = lv;
                hv = to_tf32(v.z); lv = to_tf32(v.z - hv);
                Bh[(c4 + 2) * 72 + row] = hv; Bl[(c4 + 2) * 72 + row] = lv;
                hv = to_tf32(v.w); lv = to_tf32(v.w - hv);
                Bh[(c4 + 3) * 72 + row] = hv; Bl[(c4 + 3) * 72 + row] = lv;
            }
        }
        __syncthreads();

#pragma unroll
        for (int ks = 0; ks < 4; ks++) {
            const int k = ks * 8;
            uint32_t ah[2][4], al[2][4], bh[4][2], bl[4][2];
#pragma unroll
            for (int mt = 0; mt < 2; mt++) {
                int r = wm * 32 + mt * 16 + g;
                ah[mt][0] = __float_as_uint(Ah[(r    ) * 36 + k + q]);
                ah[mt][1] = __float_as_uint(Ah[(r + 8) * 36 + k + q]);
                ah[mt][2] = __float_as_uint(Ah[(r    ) * 36 + k + q + 4]);
                ah[mt][3] = __float_as_uint(Ah[(r + 8) * 36 + k + q + 4]);
                al[mt][0] = __float_as_uint(Al[(r    ) * 36 + k + q]);
                al[mt][1] = __float_as_uint(Al[(r + 8) * 36 + k + q]);
                al[mt][2] = __float_as_uint(Al[(r    ) * 36 + k + q + 4]);
                al[mt][3] = __float_as_uint(Al[(r + 8) * 36 + k + q + 4]);
            }
#pragma unroll
            for (int nt = 0; nt < 4; nt++) {
                int nn = wn * 32 + nt * 8 + g;
                bh[nt][0] = __float_as_uint(Bh[(k + q    ) * 72 + nn]);
                bh[nt][1] = __float_as_uint(Bh[(k + q + 4) * 72 + nn]);
                bl[nt][0] = __float_as_uint(Bl[(k + q    ) * 72 + nn]);
                bl[nt][1] = __float_as_uint(Bl[(k + q + 4) * 72 + nn]);
            }
#pragma unroll
            for (int mt = 0; mt < 2; mt++)
#pragma unroll
                for (int nt = 0; nt < 4; nt++) {
                    mma_tf32(acc[mt][nt], ah[mt], bl[nt]);
                    mma_tf32(acc[mt][nt], al[mt], bh[nt]);
                    mma_tf32(acc[mt][nt], ah[mt], bh[nt]);
                }
        }
        __syncthreads();
    }

#pragma unroll
    for (int mt = 0; mt < 2; mt++) {
#pragma unroll
        for (int nt = 0; nt < 4; nt++) {
            int r0 = m0 + wm * 32 + mt * 16 + g;
            int c0 = n0 + wn * 32 + nt * 8 + q * 2;
#pragma unroll
            for (int hf = 0; hf < 2; hf++) {
                int row = r0 + hf * 8;
                float2 o2;
                o2.x = acc[mt][nt][hf * 2 + 0];
                o2.y = acc[mt][nt][hf * 2 + 1];
                *(float2*)(C + (size_t)row * N + c0) = o2;
            }
        }
    }
}

// ---------------- launcher ----------------
extern "C" void kernel_launch(void* const* d_in, const int* in_sizes, int n_in,
                              void* d_out, int out_size) {
    const int*   ids    = (const int*)d_in[0];
    const int*   sp     = (const int*)d_in[1];
    const float* emb    = (const float*)d_in[2];
    const float* ln1_g  = (const float*)d_in[3];
    const float* ln1_b  = (const float*)d_in[4];
    const float* Wqkv   = (const float*)d_in[5];
    const float* bqkv   = (const float*)d_in[6];
    const float* Wo     = (const float*)d_in[7];
    const float* bo     = (const float*)d_in[8];
    const float* ln2_g  = (const float*)d_in[9];
    const float* ln2_b  = (const float*)d_in[10];
    const float* Wfc    = (const float*)d_in[11];
    const float* bfc    = (const float*)d_in[12];
    const float* Wproj  = (const float*)d_in[13];
    const float* bproj  = (const float*)d_in[14];
    const float* lnf_g  = (const float*)d_in[15];
    const float* lnf_b  = (const float*)d_in[16];
    float* out = (float*)d_out;

    float *x, *h, *qkv;
    half *hh, *attn_h, *mid_h, *wqkv_t, *wo_t, *wfc_t, *wproj_t;
    cudaGetSymbolAddress((void**)&x,       g_x);
    cudaGetSymbolAddress((void**)&h,       g_h);
    cudaGetSymbolAddress((void**)&qkv,     g_qkv);
    cudaGetSymbolAddress((void**)&hh,      g_hh);
    cudaGetSymbolAddress((void**)&attn_h,  g_attn_h);
    cudaGetSymbolAddress((void**)&mid_h,   g_mid_h);
    cudaGetSymbolAddress((void**)&wqkv_t,  g_Wqkv_t);
    cudaGetSymbolAddress((void**)&wo_t,    g_Wo_t);
    cudaGetSymbolAddress((void**)&wfc_t,   g_Wfc_t);
    cudaGetSymbolAddress((void**)&wproj_t, g_Wproj_t);

    cudaFuncSetAttribute(attn_kernel, cudaFuncAttributeMaxDynamicSharedMemorySize, ATTN_SMEM_BYTES);
    cudaFuncSetAttribute(gemm_h16<false, false, false>, cudaFuncAttributeMaxDynamicSharedMemorySize, GEMM_SMEM);
    cudaFuncSetAttribute(gemm_h16<false, true, false>,  cudaFuncAttributeMaxDynamicSharedMemorySize, GEMM_SMEM);
    cudaFuncSetAttribute(gemm_h16<true, false, true>,   cudaFuncAttributeMaxDynamicSharedMemorySize, GEMM_SMEM);

    wtrans_kernel<<<dim3(3 * Hx / 32, Hx / 32, NLx), 256>>>(Wqkv, wqkv_t, Hx, 3 * Hx);
    wtrans_kernel<<<dim3(Hx / 32, Hx / 32, NLx), 256>>>(Wo, wo_t, Hx, Hx);
    wtrans_kernel<<<dim3(Fx / 32, Hx / 32, NLx), 256>>>(Wfc, wfc_t, Hx, Fx);
    wtrans_kernel<<<dim3(Hx / 32, Fx / 32, NLx), 256>>>(Wproj, wproj_t, Fx, Hx);

    embed_kernel<<<Mx, 256>>>(ids, emb, x);

    for (int l = 0; l < NLx; l++) {
        ln_kernel<true><<<Mx / 8, 256>>>(x, ln1_g + l * Hx, ln1_b + l * Hx, nullptr, hh);
        gemm_h16<false, false, false><<<dim3(3 * Hx / 128, Mx / 128), 256, GEMM_SMEM>>>(
            hh, wqkv_t + (size_t)l * 3 * Hx * Hx, bqkv + (size_t)l * 3 * Hx, nullptr,
            qkv, nullptr, Mx, 3 * Hx, Hx);
        attn_kernel<<<dim3(Sx / 64, Bx * NHx), 128, ATTN_SMEM_BYTES>>>(qkv, sp, attn_h);
        gemm_h16<false, true, false><<<dim3(Hx / 128, Mx / 128), 256, GEMM_SMEM>>>(
            attn_h, wo_t + (size_t)l * Hx * Hx, bo + (size_t)l * Hx, x,
            x, nullptr, Mx, Hx, Hx);
        ln_kernel<true><<<Mx / 8, 256>>>(x, ln2_g + l * Hx, ln2_b + l * Hx, nullptr, hh);
        gemm_h16<true, false, true><<<dim3(Fx / 128, Mx / 128), 256, GEMM_SMEM>>>(
            hh, wfc_t + (size_t)l * Fx * Hx, bfc + (size_t)l * Fx, nullptr,
            nullptr, mid_h, Mx, Fx, Hx);
        gemm_h16<false, true, false><<<dim3(Hx / 128, Mx / 128), 256, GEMM_SMEM>>>(
            mid_h, wproj_t + (size_t)l * Hx * Fx, bproj + (size_t)l * Hx, x,
            x, nullptr, Mx, Hx, Fx);
    }

    ln_kernel<false><<<Mx / 8, 256>>>(x, lnf_g, lnf_b, h, nullptr);
    gemm_logits<<<dim3(Vx / 64, Mx / 64), 128>>>(h, emb, out, Mx, Vx, Hx);
}

// round 10
// speedup vs baseline: 2.0576x; 1.0440x over previous
#include <cuda_runtime.h>
#include <cuda_fp16.h>
#include <math.h>
#include <stdint.h>

#define Bx  16
#define Sx  512
#define Vx  512
#define Hx  1024
#define NLx 8
#define NHx 16
#define DHx 64
#define Fx  4096
#define Mx  (Bx*Sx)

#define LOG2E 1.4426950408889634f

// ---------------- scratch ----------------
__device__ float g_x[Mx*Hx];
__device__ half  g_qkv_h[Mx*3*Hx];
__device__ half  g_hh[Mx*Hx];
__device__ half  g_attn_h[Mx*Hx];
__device__ half  g_mid_h[(size_t)Mx*Fx];
__device__ half  g_hhi[Mx*Hx];
__device__ half  g_hlo[Mx*Hx];
__device__ half  g_ehi[Vx*Hx];
__device__ half  g_elo[Vx*Hx];
__device__ half  g_Wqkv_t[(size_t)NLx*3*Hx*Hx];
__device__ half  g_Wo_t[(size_t)NLx*Hx*Hx];
__device__ half  g_Wfc_t[(size_t)NLx*Fx*Hx];
__device__ half  g_Wproj_t[(size_t)NLx*Hx*Fx];

// ---------------- helpers ----------------
__device__ __forceinline__ float ex2(float x) {
    float r;
    asm("ex2.approx.f32 %0, %1;" : "=f"(r) : "f"(x));
    return r;
}
__device__ __forceinline__ void mma_f16(float* c, const uint32_t* a, const uint32_t* b) {
    asm volatile(
        "mma.sync.aligned.m16n8k16.row.col.f32.f16.f16.f32 "
        "{%0,%1,%2,%3}, {%4,%5,%6,%7}, {%8,%9}, {%0,%1,%2,%3};\n"
        : "+f"(c[0]), "+f"(c[1]), "+f"(c[2]), "+f"(c[3])
        : "r"(a[0]), "r"(a[1]), "r"(a[2]), "r"(a[3]), "r"(b[0]), "r"(b[1]));
}
__device__ __forceinline__ void ldsm_x4(uint32_t& r0, uint32_t& r1, uint32_t& r2, uint32_t& r3,
                                        uint32_t addr) {
    asm volatile("ldmatrix.sync.aligned.m8n8.x4.shared.b16 {%0,%1,%2,%3}, [%4];"
                 : "=r"(r0), "=r"(r1), "=r"(r2), "=r"(r3) : "r"(addr));
}
__device__ __forceinline__ void ldsm_x4_t(uint32_t& r0, uint32_t& r1, uint32_t& r2, uint32_t& r3,
                                          uint32_t addr) {
    asm volatile("ldmatrix.sync.aligned.m8n8.x4.trans.shared.b16 {%0,%1,%2,%3}, [%4];"
                 : "=r"(r0), "=r"(r1), "=r"(r2), "=r"(r3) : "r"(addr));
}
__device__ __forceinline__ void cp_async16(void* smem_dst, const void* gmem_src) {
    uint32_t s = (uint32_t)__cvta_generic_to_shared(smem_dst);
    asm volatile("cp.async.cg.shared.global [%0], [%1], 16;\n" :: "r"(s), "l"(gmem_src));
}
__device__ __forceinline__ void cp_commit() { asm volatile("cp.async.commit_group;\n"); }
__device__ __forceinline__ void cp_wait0() { asm volatile("cp.async.wait_group 0;\n"); }
__device__ __forceinline__ void cp_wait2() { asm volatile("cp.async.wait_group 2;\n"); }
__device__ __forceinline__ float gelu_f(float v) {
    return 0.5f * v * (1.0f + tanhf(0.7978845608028654f * (v + 0.044715f * v * v * v)));
}

// ---------------- weight transpose+convert ----------------
__global__ __launch_bounds__(256) void wtrans_kernel(const float* __restrict__ W,
                                                     half* __restrict__ Wt,
                                                     int K, int N) {
    __shared__ float tile[32][33];
    const size_t lsz = (size_t)K * N;
    const float* Wl = W + blockIdx.z * lsz;
    half* Wtl = Wt + blockIdx.z * lsz;
    int n0 = blockIdx.x * 32, k0 = blockIdx.y * 32;
    int tx = threadIdx.x & 31, ty = threadIdx.x >> 5;
#pragma unroll
    for (int i = 0; i < 4; i++)
        tile[ty + i * 8][tx] = Wl[(size_t)(k0 + ty + i * 8) * N + n0 + tx];
    __syncthreads();
#pragma unroll
    for (int i = 0; i < 4; i++)
        Wtl[(size_t)(n0 + ty + i * 8) * K + k0 + tx] = __float2half_rn(tile[tx][ty + i * 8]);
}

// ---------------- emb hi/lo split ----------------
__global__ __launch_bounds__(256) void esplit_kernel(const float* __restrict__ src,
                                                     half* __restrict__ hi,
                                                     half* __restrict__ lo) {
    int idx = blockIdx.x * 256 + threadIdx.x;
    float4 v = ((const float4*)src)[idx];
    half h0 = __float2half_rn(v.x), h1 = __float2half_rn(v.y);
    half h2 = __float2half_rn(v.z), h3 = __float2half_rn(v.w);
    half l0 = __float2half_rn(v.x - __half2float(h0));
    half l1 = __float2half_rn(v.y - __half2float(h1));
    half l2 = __float2half_rn(v.z - __half2float(h2));
    half l3 = __float2half_rn(v.w - __half2float(h3));
    half2 hh0; hh0.x = h0; hh0.y = h1;
    half2 hh1; hh1.x = h2; hh1.y = h3;
    half2 ll0; ll0.x = l0; ll0.y = l1;
    half2 ll1; ll1.x = l2; ll1.y = l3;
    *(half2*)(hi + idx * 4) = hh0; *(half2*)(hi + idx * 4 + 2) = hh1;
    *(half2*)(lo + idx * 4) = ll0; *(half2*)(lo + idx * 4 + 2) = ll1;
}

// ---------------- embedding ----------------
__global__ __launch_bounds__(256) void embed_kernel(const int* __restrict__ ids,
                                                    const float* __restrict__ emb,
                                                    float* __restrict__ out) {
    int m = blockIdx.x, t = threadIdx.x;
    int id = ids[m];
    ((float4*)(out + (size_t)m * Hx))[t] = ((const float4*)(emb + (size_t)id * Hx))[t];
}

// ---------------- layernorm: warp-per-row; MODE 1=half, 2=hi/lo halves ------
template<int MODE>
__global__ __launch_bounds__(256) void ln_kernel(const float* __restrict__ x,
                                                 const float* __restrict__ g,
                                                 const float* __restrict__ b,
                                                 half* __restrict__ outh,
                                                 half* __restrict__ outl) {
    const int lane = threadIdx.x & 31;
    const int m = blockIdx.x * 8 + (threadIdx.x >> 5);
    const float4* xr = (const float4*)(x + (size_t)m * Hx);

    float4 v[8];
    float s = 0.f;
#pragma unroll
    for (int i = 0; i < 8; i++) {
        v[i] = xr[lane + i * 32];
        s += v[i].x + v[i].y + v[i].z + v[i].w;
    }
#pragma unroll
    for (int o = 16; o; o >>= 1) s += __shfl_xor_sync(0xffffffffu, s, o);
    float mu = s * (1.0f / Hx);

    float s2 = 0.f;
#pragma unroll
    for (int i = 0; i < 8; i++) {
        float d0 = v[i].x - mu, d1 = v[i].y - mu, d2 = v[i].z - mu, d3 = v[i].w - mu;
        s2 += d0*d0 + d1*d1 + d2*d2 + d3*d3;
    }
#pragma unroll
    for (int o = 16; o; o >>= 1) s2 += __shfl_xor_sync(0xffffffffu, s2, o);
    float inv = rsqrtf(s2 * (1.0f / Hx) + 1e-5f);

#pragma unroll
    for (int i = 0; i < 8; i++) {
        float4 gg = ((const float4*)g)[lane + i * 32];
        float4 bb = ((const float4*)b)[lane + i * 32];
        float o0 = (v[i].x - mu) * inv * gg.x + bb.x;
        float o1 = (v[i].y - mu) * inv * gg.y + bb.y;
        float o2 = (v[i].z - mu) * inv * gg.z + bb.z;
        float o3 = (v[i].w - mu) * inv * gg.w + bb.w;
        int c = (lane + i * 32) * 4;
        if (MODE == 1) {
            *(half2*)(outh + (size_t)m * Hx + c) = __floats2half2_rn(o0, o1);
            *(half2*)(outh + (size_t)m * Hx + c + 2) = __floats2half2_rn(o2, o3);
        } else {
            half h0 = __float2half_rn(o0), h1 = __float2half_rn(o1);
            half h2 = __float2half_rn(o2), h3 = __float2half_rn(o3);
            half2 hh0; hh0.x = h0; hh0.y = h1;
            half2 hh1; hh1.x = h2; hh1.y = h3;
            *(half2*)(outh + (size_t)m * Hx + c) = hh0;
            *(half2*)(outh + (size_t)m * Hx + c + 2) = hh1;
            *(half2*)(outl + (size_t)m * Hx + c) =
                __floats2half2_rn(o0 - __half2float(h0), o1 - __half2float(h1));
            *(half2*)(outl + (size_t)m * Hx + c + 2) =
                __floats2half2_rn(o2 - __half2float(h2), o3 - __half2float(h3));
        }
    }
}

// ======= fp16 GEMM, 4-stage cp.async + ldmatrix =============================
#define HST 40
#define NSTAGE 4
#define STG_HALVES (128 * HST)
#define GEMM_SMEM (NSTAGE * 2 * STG_HALVES * 2)

template<bool GELU, bool RESID, bool OUT_HALF>
__global__ __launch_bounds__(256, 2) void gemm_h16(const half* __restrict__ A,
                                                   const half* __restrict__ Bw,
                                                   const float* __restrict__ bias,
                                                   const float* __restrict__ R,
                                                   float* __restrict__ C,
                                                   half* __restrict__ Ch,
                                                   int M, int N, int K) {
    extern __shared__ half smh[];
    const int t = threadIdx.x;
    const int warp = t >> 5, lane = t & 31;
    const int g = lane >> 2, q = lane & 3;
    const int wm = warp >> 1, wn = warp & 1;
    const int m0 = blockIdx.y * 128, n0 = blockIdx.x * 128;

    const int f_row = t >> 1, f_ch = (t & 1) * 16;
    const uint32_t smbase = (uint32_t)__cvta_generic_to_shared(smh);

    const int a_off = (wm * 32 + (lane & 15)) * HST + (lane >> 4) * 8;
    const int b_off = (wn * 64 + ((lane >> 4) * 8) + (lane & 7)) * HST + ((lane >> 3) & 1) * 8;

    float acc[2][8][4];
#pragma unroll
    for (int mt = 0; mt < 2; mt++)
#pragma unroll
        for (int nt = 0; nt < 8; nt++)
#pragma unroll
            for (int r = 0; r < 4; r++) acc[mt][nt][r] = 0.f;

    const half* Arow = A + (size_t)(m0 + f_row) * K + f_ch;
    const half* Brow = Bw + (size_t)(n0 + f_row) * K + f_ch;

#pragma unroll
    for (int s = 0; s < NSTAGE - 1; s++) {
        half* as = smh + s * 2 * STG_HALVES;
        half* bs = as + STG_HALVES;
        cp_async16(&as[f_row * HST + f_ch],     Arow + s * 32);
        cp_async16(&as[f_row * HST + f_ch + 8], Arow + s * 32 + 8);
        cp_async16(&bs[f_row * HST + f_ch],     Brow + s * 32);
        cp_async16(&bs[f_row * HST + f_ch + 8], Brow + s * 32 + 8);
        cp_commit();
    }

    const int T = K >> 5;
    for (int i = 0; i < T; i++) {
        const int s = i & (NSTAGE - 1);
        cp_wait2();
        __syncthreads();

        if (i + NSTAGE - 1 < T) {
            const int sn = (i + NSTAGE - 1) & (NSTAGE - 1);
            const int kn = (i + NSTAGE - 1) * 32;
            half* as = smh + sn * 2 * STG_HALVES;
            half* bs = as + STG_HALVES;
            cp_async16(&as[f_row * HST + f_ch],     Arow + kn);
            cp_async16(&as[f_row * HST + f_ch + 8], Arow + kn + 8);
            cp_async16(&bs[f_row * HST + f_ch],     Brow + kn);
            cp_async16(&bs[f_row * HST + f_ch + 8], Brow + kn + 8);
        }
        cp_commit();

        const uint32_t as_b = smbase + (uint32_t)(s * 2 * STG_HALVES) * 2;
        const uint32_t bs_b = as_b + (uint32_t)STG_HALVES * 2;
#pragma unroll
        for (int ks = 0; ks < 2; ks++) {
            const int k = ks * 16;
            uint32_t af[2][4], bf[8][2];
#pragma unroll
            for (int mt = 0; mt < 2; mt++)
                ldsm_x4(af[mt][0], af[mt][1], af[mt][2], af[mt][3],
                        as_b + (uint32_t)(a_off + mt * 16 * HST + k) * 2);
#pragma unroll
            for (int p = 0; p < 4; p++)
                ldsm_x4(bf[2*p][0], bf[2*p][1], bf[2*p+1][0], bf[2*p+1][1],
                        bs_b + (uint32_t)(b_off + p * 16 * HST + k) * 2);
#pragma unroll
            for (int mt = 0; mt < 2; mt++)
#pragma unroll
                for (int nt = 0; nt < 8; nt++)
                    mma_f16(acc[mt][nt], af[mt], bf[nt]);
        }
    }

#pragma unroll
    for (int mt = 0; mt < 2; mt++) {
#pragma unroll
        for (int nt = 0; nt < 8; nt++) {
            int r0 = m0 + wm * 32 + mt * 16 + g;
            int c0 = n0 + wn * 64 + nt * 8 + q * 2;
            float b0 = bias ? bias[c0] : 0.f;
            float b1 = bias ? bias[c0 + 1] : 0.f;
#pragma unroll
            for (int hf = 0; hf < 2; hf++) {
                int row = r0 + hf * 8;
                float v0 = acc[mt][nt][hf * 2 + 0] + b0;
                float v1 = acc[mt][nt][hf * 2 + 1] + b1;
                if (GELU) { v0 = gelu_f(v0); v1 = gelu_f(v1); }
                if (RESID) {
                    const float2 rr = *(const float2*)(R + (size_t)row * N + c0);
                    v0 += rr.x; v1 += rr.y;
                }
                if (OUT_HALF) {
                    *(half2*)(Ch + (size_t)row * N + c0) = __floats2half2_rn(v0, v1);
                } else {
                    float2 o2; o2.x = v0; o2.y = v1;
                    *(float2*)(C + (size_t)row * N + c0) = o2;
                }
            }
        }
    }
}

// ---------------- fused flash attention: fp16 HMMA, half qkv input ----------
#define AHS 72
#define ATTN_SMEM_BYTES (4 * 64 * AHS * 2)

__global__ __launch_bounds__(128) void attn_kernel(const half* __restrict__ qkv,
                                                   const int* __restrict__ sp,
                                                   half* __restrict__ attn) {
    extern __shared__ half smah[];
    half* Qs = smah;
    half* Ks = Qs + 64 * AHS;
    half* Vs = Ks + 64 * AHS;
    half* Ps = Vs + 64 * AHS;
    const uint32_t qs_b = (uint32_t)__cvta_generic_to_shared(Qs);
    const uint32_t ks_b = (uint32_t)__cvta_generic_to_shared(Ks);
    const uint32_t vs_b = (uint32_t)__cvta_generic_to_shared(Vs);
    const uint32_t ps_b = (uint32_t)__cvta_generic_to_shared(Ps);

    const int it = blockIdx.x, bn = blockIdx.y;
    const int b = bn >> 4, n = bn & 15;
    const int t = threadIdx.x, w = t >> 5, lane = t & 31;
    const int g = lane >> 2, q = lane & 3;
    const int i0 = it * 64;
    const int spv = sp[b];
    const float slope2 = exp2f(-0.5f * (float)(n + 1)) * LOG2E;
    const float qs2 = 0.125f * LOG2E;   // applied to QK^T output

    // ---- fill Q (raw half copy via cp.async)
#pragma unroll
    for (int l = 0; l < 4; l++) {
        int e = t + l * 128;
        int row = e >> 3, c8 = (e & 7) * 8;
        cp_async16(&Qs[row * AHS + c8],
                   qkv + (size_t)(b * Sx + i0 + row) * 3072 + n * 64 + c8);
    }
    cp_commit();
    cp_wait0();
    __syncthreads();

    const int r0 = w * 16 + g;
    const int a_off = (w * 16 + (lane & 15)) * AHS + (lane >> 4) * 8;
    uint32_t qf[4][4];
#pragma unroll
    for (int kk = 0; kk < 4; kk++)
        ldsm_x4(qf[kk][0], qf[kk][1], qf[kk][2], qf[kk][3],
                qs_b + (uint32_t)(a_off + kk * 16) * 2);

    const int bk_off = (((lane >> 4) * 8) + (lane & 7)) * AHS + ((lane >> 3) & 1) * 8;
    const int vt_off = (((lane >> 3) & 1) * 8 + (lane & 7)) * AHS + (lane >> 4) * 8;

    float o[8][4];
#pragma unroll
    for (int nt = 0; nt < 8; nt++)
#pragma unroll
        for (int c = 0; c < 4; c++) o[nt][c] = 0.f;
    float m0 = -1e30f, m1 = -1e30f, l0 = 0.f, l1 = 0.f;

    const int rowA = i0 + r0, rowB = rowA + 8;

    for (int jt = 0; jt <= it; jt++) {
        const int j0 = jt * 64;
        __syncthreads();
#pragma unroll
        for (int l = 0; l < 4; l++) {
            int e = t + l * 128;
            int row = e >> 3, c8 = (e & 7) * 8;
            const half* base = qkv + (size_t)(b * Sx + j0 + row) * 3072 + n * 64 + c8;
            cp_async16(&Ks[row * AHS + c8], base + 1024);
            cp_async16(&Vs[row * AHS + c8], base + 2048);
        }
        cp_commit();
        cp_wait0();
        __syncthreads();

        // ---- QK^T
        float s[8][4];
#pragma unroll
        for (int nt = 0; nt < 8; nt++)
#pragma unroll
            for (int c = 0; c < 4; c++) s[nt][c] = 0.f;
#pragma unroll
        for (int kk = 0; kk < 4; kk++) {
            uint32_t bf[8][2];
#pragma unroll
            for (int p = 0; p < 4; p++)
                ldsm_x4(bf[2*p][0], bf[2*p][1], bf[2*p+1][0], bf[2*p+1][1],
                        ks_b + (uint32_t)(bk_off + p * 16 * AHS + kk * 16) * 2);
#pragma unroll
            for (int nt = 0; nt < 8; nt++)
                mma_f16(s[nt], qf[kk], bf[nt]);
        }

        // ---- scale + bias + mask (log2 domain)
#pragma unroll
        for (int nt = 0; nt < 8; nt++) {
#pragma unroll
            for (int c = 0; c < 4; c++) {
                int i = (c < 2) ? rowA : rowB;
                int j = j0 + nt * 8 + 2 * q + (c & 1);
                bool allowed = (j <= i) && !((i >= spv) && (j < spv));
                s[nt][c] = allowed ? fmaf(s[nt][c], qs2, -slope2 * (float)(i - j)) : -1e30f;
            }
        }

        // ---- online softmax
        float mx0 = -1e30f, mx1 = -1e30f;
#pragma unroll
        for (int nt = 0; nt < 8; nt++) {
            mx0 = fmaxf(mx0, fmaxf(s[nt][0], s[nt][1]));
            mx1 = fmaxf(mx1, fmaxf(s[nt][2], s[nt][3]));
        }
        mx0 = fmaxf(mx0, __shfl_xor_sync(0xffffffffu, mx0, 1));
        mx0 = fmaxf(mx0, __shfl_xor_sync(0xffffffffu, mx0, 2));
        mx1 = fmaxf(mx1, __shfl_xor_sync(0xffffffffu, mx1, 1));
        mx1 = fmaxf(mx1, __shfl_xor_sync(0xffffffffu, mx1, 2));
        float mn0 = fmaxf(m0, mx0), mn1 = fmaxf(m1, mx1);
        float al0 = ex2(m0 - mn0), al1 = ex2(m1 - mn1);

        float sum0 = 0.f, sum1 = 0.f;
#pragma unroll
        for (int nt = 0; nt < 8; nt++) {
            float p0 = ex2(s[nt][0] - mn0);
            float p1 = ex2(s[nt][1] - mn0);
            float p2 = ex2(s[nt][2] - mn1);
            float p3 = ex2(s[nt][3] - mn1);
            sum0 += p0 + p1; sum1 += p2 + p3;
            *(half2*)&Ps[(r0    ) * AHS + nt * 8 + 2 * q] = __floats2half2_rn(p0, p1);
            *(half2*)&Ps[(r0 + 8) * AHS + nt * 8 + 2 * q] = __floats2half2_rn(p2, p3);
        }
        sum0 += __shfl_xor_sync(0xffffffffu, sum0, 1);
        sum0 += __shfl_xor_sync(0xffffffffu, sum0, 2);
        sum1 += __shfl_xor_sync(0xffffffffu, sum1, 1);
        sum1 += __shfl_xor_sync(0xffffffffu, sum1, 2);
        l0 = l0 * al0 + sum0;
        l1 = l1 * al1 + sum1;
        m0 = mn0; m1 = mn1;
#pragma unroll
        for (int nt = 0; nt < 8; nt++) {
            o[nt][0] *= al0; o[nt][1] *= al0;
            o[nt][2] *= al1; o[nt][3] *= al1;
        }
        __syncwarp();

        // ---- P @ V
#pragma unroll
        for (int kk = 0; kk < 4; kk++) {
            uint32_t pf[4];
            ldsm_x4(pf[0], pf[1], pf[2], pf[3],
                    ps_b + (uint32_t)(a_off + kk * 16) * 2);
            uint32_t bf[8][2];
#pragma unroll
            for (int p = 0; p < 4; p++)
                ldsm_x4_t(bf[2*p][0], bf[2*p][1], bf[2*p+1][0], bf[2*p+1][1],
                          vs_b + (uint32_t)(vt_off + kk * 16 * AHS + p * 16) * 2);
#pragma unroll
            for (int nt = 0; nt < 8; nt++)
                mma_f16(o[nt], pf, bf[nt]);
        }
    }

    const float inv0 = 1.0f / l0, inv1 = 1.0f / l1;
#pragma unroll
    for (int nt = 0; nt < 8; nt++) {
        *(half2*)(attn + (size_t)(b * Sx + rowA) * Hx + n * 64 + nt * 8 + 2 * q) =
            __floats2half2_rn(o[nt][0] * inv0, o[nt][1] * inv0);
        *(half2*)(attn + (size_t)(b * Sx + rowB) * Hx + n * 64 + nt * 8 + 2 * q) =
            __floats2half2_rn(o[nt][2] * inv1, o[nt][3] * inv1);
    }
}

// ---------------- logits: fp16 hi/lo 3-term GEMM, 2-stage ------------------
// C = (Ahi+Alo) @ (Bhi+Blo)^T ≈ Ahi·Bhi + Ahi·Blo + Alo·Bhi (fp32 accum)
#define L3_STG (128 * HST)
#define L3_STAGE (4 * L3_STG)
#define L3_SMEM (2 * L3_STAGE * 2)   // 81920 B

__global__ __launch_bounds__(256) void gemm_logits3(const half* __restrict__ Ahi,
                                                    const half* __restrict__ Alo,
                                                    const half* __restrict__ Bhi,
                                                    const half* __restrict__ Blo,
                                                    float* __restrict__ C,
                                                    int M, int N, int K) {
    extern __shared__ half smh[];
    const int t = threadIdx.x;
    const int warp = t >> 5, lane = t & 31;
    const int g = lane >> 2, q = lane & 3;
    const int wm = warp >> 1, wn = warp & 1;
    const int m0 = blockIdx.y * 128, n0 = blockIdx.x * 128;

    const int f_row = t >> 1, f_ch = (t & 1) * 16;
    const uint32_t smbase = (uint32_t)__cvta_generic_to_shared(smh);

    const int a_off = (wm * 32 + (lane & 15)) * HST + (lane >> 4) * 8;
    const int b_off = (wn * 64 + ((lane >> 4) * 8) + (lane & 7)) * HST + ((lane >> 3) & 1) * 8;

    float acc[2][8][4];
#pragma unroll
    for (int mt = 0; mt < 2; mt++)
#pragma unroll
        for (int nt = 0; nt < 8; nt++)
#pragma unroll
            for (int r = 0; r < 4; r++) acc[mt][nt][r] = 0.f;

    const half* ArH = Ahi + (size_t)(m0 + f_row) * K + f_ch;
    const half* ArL = Alo + (size_t)(m0 + f_row) * K + f_ch;
    const half* BrH = Bhi + (size_t)(n0 + f_row) * K + f_ch;
    const half* BrL = Blo + (size_t)(n0 + f_row) * K + f_ch;
    const int so = f_row * HST + f_ch;

    // prologue: stage 0
    {
        half* st = smh;
        cp_async16(&st[so], ArH);                     cp_async16(&st[so + 8], ArH + 8);
        cp_async16(&st[L3_STG + so], ArL);            cp_async16(&st[L3_STG + so + 8], ArL + 8);
        cp_async16(&st[2 * L3_STG + so], BrH);        cp_async16(&st[2 * L3_STG + so + 8], BrH + 8);
        cp_async16(&st[3 * L3_STG + so], BrL);        cp_async16(&st[3 * L3_STG + so + 8], BrL + 8);
        cp_commit();
    }

    const int T = K >> 5;
    for (int i = 0; i < T; i++) {
        cp_wait0();
        __syncthreads();

        if (i + 1 < T) {
            const int kn = (i + 1) * 32;
            half* st = smh + ((i + 1) & 1) * L3_STAGE;
            cp_async16(&st[so], ArH + kn);                cp_async16(&st[so + 8], ArH + kn + 8);
            cp_async16(&st[L3_STG + so], ArL + kn);       cp_async16(&st[L3_STG + so + 8], ArL + kn + 8);
            cp_async16(&st[2 * L3_STG + so], BrH + kn);   cp_async16(&st[2 * L3_STG + so + 8], BrH + kn + 8);
            cp_async16(&st[3 * L3_STG + so], BrL + kn);   cp_async16(&st[3 * L3_STG + so + 8], BrL + kn + 8);
        }
        cp_commit();

        const uint32_t st_b  = smbase + (uint32_t)((i & 1) * L3_STAGE) * 2;
        const uint32_t ah_b = st_b;
        const uint32_t al_b = st_b + (uint32_t)L3_STG * 2;
        const uint32_t bh_b = st_b + (uint32_t)(2 * L3_STG) * 2;
        const uint32_t bl_b = st_b + (uint32_t)(3 * L3_STG) * 2;
#pragma unroll
        for (int ks = 0; ks < 2; ks++) {
            const int k = ks * 16;
            uint32_t ah[2][4], al[2][4], bh[8][2], bl[8][2];
#pragma unroll
            for (int mt = 0; mt < 2; mt++) {
                ldsm_x4(ah[mt][0], ah[mt][1], ah[mt][2], ah[mt][3],
                        ah_b + (uint32_t)(a_off + mt * 16 * HST + k) * 2);
                ldsm_x4(al[mt][0], al[mt][1], al[mt][2], al[mt][3],
                        al_b + (uint32_t)(a_off + mt * 16 * HST + k) * 2);
            }
#pragma unroll
            for (int p = 0; p < 4; p++) {
                ldsm_x4(bh[2*p][0], bh[2*p][1], bh[2*p+1][0], bh[2*p+1][1],
                        bh_b + (uint32_t)(b_off + p * 16 * HST + k) * 2);
                ldsm_x4(bl[2*p][0], bl[2*p][1], bl[2*p+1][0], bl[2*p+1][1],
                        bl_b + (uint32_t)(b_off + p * 16 * HST + k) * 2);
            }
#pragma unroll
            for (int mt = 0; mt < 2; mt++)
#pragma unroll
                for (int nt = 0; nt < 8; nt++) {
                    mma_f16(acc[mt][nt], ah[mt], bl[nt]);
                    mma_f16(acc[mt][nt], al[mt], bh[nt]);
                    mma_f16(acc[mt][nt], ah[mt], bh[nt]);
                }
        }
    }

#pragma unroll
    for (int mt = 0; mt < 2; mt++) {
#pragma unroll
        for (int nt = 0; nt < 8; nt++) {
            int r0 = m0 + wm * 32 + mt * 16 + g;
            int c0 = n0 + wn * 64 + nt * 8 + q * 2;
#pragma unroll
            for (int hf = 0; hf < 2; hf++) {
                int row = r0 + hf * 8;
                float2 o2;
                o2.x = acc[mt][nt][hf * 2 + 0];
                o2.y = acc[mt][nt][hf * 2 + 1];
                *(float2*)(C + (size_t)row * N + c0) = o2;
            }
        }
    }
}

// ---------------- launcher ----------------
extern "C" void kernel_launch(void* const* d_in, const int* in_sizes, int n_in,
                              void* d_out, int out_size) {
    const int*   ids    = (const int*)d_in[0];
    const int*   sp     = (const int*)d_in[1];
    const float* emb    = (const float*)d_in[2];
    const float* ln1_g  = (const float*)d_in[3];
    const float* ln1_b  = (const float*)d_in[4];
    const float* Wqkv   = (const float*)d_in[5];
    const float* bqkv   = (const float*)d_in[6];
    const float* Wo     = (const float*)d_in[7];
    const float* bo     = (const float*)d_in[8];
    const float* ln2_g  = (const float*)d_in[9];
    const float* ln2_b  = (const float*)d_in[10];
    const float* Wfc    = (const float*)d_in[11];
    const float* bfc    = (const float*)d_in[12];
    const float* Wproj  = (const float*)d_in[13];
    const float* bproj  = (const float*)d_in[14];
    const float* lnf_g  = (const float*)d_in[15];
    const float* lnf_b  = (const float*)d_in[16];
    float* out = (float*)d_out;

    float* x;
    half *qkv_h, *hh, *attn_h, *mid_h, *hhi, *hlo, *ehi, *elo;
    half *wqkv_t, *wo_t, *wfc_t, *wproj_t;
    cudaGetSymbolAddress((void**)&x,       g_x);
    cudaGetSymbolAddress((void**)&qkv_h,   g_qkv_h);
    cudaGetSymbolAddress((void**)&hh,      g_hh);
    cudaGetSymbolAddress((void**)&attn_h,  g_attn_h);
    cudaGetSymbolAddress((void**)&mid_h,   g_mid_h);
    cudaGetSymbolAddress((void**)&hhi,     g_hhi);
    cudaGetSymbolAddress((void**)&hlo,     g_hlo);
    cudaGetSymbolAddress((void**)&ehi,     g_ehi);
    cudaGetSymbolAddress((void**)&elo,     g_elo);
    cudaGetSymbolAddress((void**)&wqkv_t,  g_Wqkv_t);
    cudaGetSymbolAddress((void**)&wo_t,    g_Wo_t);
    cudaGetSymbolAddress((void**)&wfc_t,   g_Wfc_t);
    cudaGetSymbolAddress((void**)&wproj_t, g_Wproj_t);

    cudaFuncSetAttribute(attn_kernel, cudaFuncAttributeMaxDynamicSharedMemorySize, ATTN_SMEM_BYTES);
    cudaFuncSetAttribute(gemm_h16<false, false, true>,  cudaFuncAttributeMaxDynamicSharedMemorySize, GEMM_SMEM);
    cudaFuncSetAttribute(gemm_h16<false, true, false>,  cudaFuncAttributeMaxDynamicSharedMemorySize, GEMM_SMEM);
    cudaFuncSetAttribute(gemm_h16<true, false, true>,   cudaFuncAttributeMaxDynamicSharedMemorySize, GEMM_SMEM);
    cudaFuncSetAttribute(gemm_logits3, cudaFuncAttributeMaxDynamicSharedMemorySize, L3_SMEM);

    wtrans_kernel<<<dim3(3 * Hx / 32, Hx / 32, NLx), 256>>>(Wqkv, wqkv_t, Hx, 3 * Hx);
    wtrans_kernel<<<dim3(Hx / 32, Hx / 32, NLx), 256>>>(Wo, wo_t, Hx, Hx);
    wtrans_kernel<<<dim3(Fx / 32, Hx / 32, NLx), 256>>>(Wfc, wfc_t, Hx, Fx);
    wtrans_kernel<<<dim3(Hx / 32, Fx / 32, NLx), 256>>>(Wproj, wproj_t, Fx, Hx);
    esplit_kernel<<<(Vx * Hx / 4) / 256, 256>>>(emb, ehi, elo);

    embed_kernel<<<Mx, 256>>>(ids, emb, x);

    for (int l = 0; l < NLx; l++) {
        ln_kernel<1><<<Mx / 8, 256>>>(x, ln1_g + l * Hx, ln1_b + l * Hx, hh, nullptr);
        gemm_h16<false, false, true><<<dim3(3 * Hx / 128, Mx / 128), 256, GEMM_SMEM>>>(
            hh, wqkv_t + (size_t)l * 3 * Hx * Hx, bqkv + (size_t)l * 3 * Hx, nullptr,
            nullptr, qkv_h, Mx, 3 * Hx, Hx);
        attn_kernel<<<dim3(Sx / 64, Bx * NHx), 128, ATTN_SMEM_BYTES>>>(qkv_h, sp, attn_h);
        gemm_h16<false, true, false><<<dim3(Hx / 128, Mx / 128), 256, GEMM_SMEM>>>(
            attn_h, wo_t + (size_t)l * Hx * Hx, bo + (size_t)l * Hx, x,
            x, nullptr, Mx, Hx, Hx);
        ln_kernel<1><<<Mx / 8, 256>>>(x, ln2_g + l * Hx, ln2_b + l * Hx, hh, nullptr);
        gemm_h16<true, false, true><<<dim3(Fx / 128, Mx / 128), 256, GEMM_SMEM>>>(
            hh, wfc_t + (size_t)l * Fx * Hx, bfc + (size_t)l * Fx, nullptr,
            nullptr, mid_h, Mx, Fx, Hx);
        gemm_h16<false, true, false><<<dim3(Hx / 128, Mx / 128), 256, GEMM_SMEM>>>(
            mid_h, wproj_t + (size_t)l * Hx * Fx, bproj + (size_t)l * Hx, x,
            x, nullptr, Mx, Hx, Fx);
    }

    ln_kernel<2><<<Mx / 8, 256>>>(x, lnf_g, lnf_b, hhi, hlo);
    gemm_logits3<<<dim3(Vx / 128, Mx / 128), 256, L3_SMEM>>>(
        hhi, hlo, ehi, elo, out, Mx, Vx, Hx);
}

// round 11
// speedup vs baseline: 2.0806x; 1.0112x over previous
#include <cuda_runtime.h>
#include <cuda_fp16.h>
#include <math.h>
#include <stdint.h>

#define Bx  16
#define Sx  512
#define Vx  512
#define Hx  1024
#define NLx 8
#define NHx 16
#define DHx 64
#define Fx  4096
#define Mx  (Bx*Sx)

#define LOG2E 1.4426950408889634f

// ---------------- scratch ----------------
__device__ float g_x[Mx*Hx];
__device__ half  g_qkv_h[Mx*3*Hx];
__device__ half  g_hh[Mx*Hx];
__device__ half  g_attn_h[Mx*Hx];
__device__ half  g_mid_h[(size_t)Mx*Fx];
__device__ half  g_hhi[Mx*Hx];
__device__ half  g_hlo[Mx*Hx];
__device__ half  g_ehi[Vx*Hx];
__device__ half  g_elo[Vx*Hx];
__device__ half  g_Wqkv_t[(size_t)NLx*3*Hx*Hx];
__device__ half  g_Wo_t[(size_t)NLx*Hx*Hx];
__device__ half  g_Wfc_t[(size_t)NLx*Fx*Hx];
__device__ half  g_Wproj_t[(size_t)NLx*Hx*Fx];

// ---------------- helpers ----------------
__device__ __forceinline__ float ex2(float x) {
    float r;
    asm("ex2.approx.f32 %0, %1;" : "=f"(r) : "f"(x));
    return r;
}
__device__ __forceinline__ void mma_f16(float* c, const uint32_t* a, const uint32_t* b) {
    asm volatile(
        "mma.sync.aligned.m16n8k16.row.col.f32.f16.f16.f32 "
        "{%0,%1,%2,%3}, {%4,%5,%6,%7}, {%8,%9}, {%0,%1,%2,%3};\n"
        : "+f"(c[0]), "+f"(c[1]), "+f"(c[2]), "+f"(c[3])
        : "r"(a[0]), "r"(a[1]), "r"(a[2]), "r"(a[3]), "r"(b[0]), "r"(b[1]));
}
__device__ __forceinline__ void ldsm_x4(uint32_t& r0, uint32_t& r1, uint32_t& r2, uint32_t& r3,
                                        uint32_t addr) {
    asm volatile("ldmatrix.sync.aligned.m8n8.x4.shared.b16 {%0,%1,%2,%3}, [%4];"
                 : "=r"(r0), "=r"(r1), "=r"(r2), "=r"(r3) : "r"(addr));
}
__device__ __forceinline__ void ldsm_x4_t(uint32_t& r0, uint32_t& r1, uint32_t& r2, uint32_t& r3,
                                          uint32_t addr) {
    asm volatile("ldmatrix.sync.aligned.m8n8.x4.trans.shared.b16 {%0,%1,%2,%3}, [%4];"
                 : "=r"(r0), "=r"(r1), "=r"(r2), "=r"(r3) : "r"(addr));
}
__device__ __forceinline__ void cp_async16(void* smem_dst, const void* gmem_src) {
    uint32_t s = (uint32_t)__cvta_generic_to_shared(smem_dst);
    asm volatile("cp.async.cg.shared.global [%0], [%1], 16;\n" :: "r"(s), "l"(gmem_src));
}
__device__ __forceinline__ void cp_commit() { asm volatile("cp.async.commit_group;\n"); }
__device__ __forceinline__ void cp_wait0() { asm volatile("cp.async.wait_group 0;\n"); }
__device__ __forceinline__ void cp_wait2() { asm volatile("cp.async.wait_group 2;\n"); }
__device__ __forceinline__ float gelu_f(float v) {
    return 0.5f * v * (1.0f + tanhf(0.7978845608028654f * (v + 0.044715f * v * v * v)));
}

// ---------------- weight transpose+convert (coalesced 16B stores) ----------
__global__ __launch_bounds__(256) void wtrans_kernel(const float* __restrict__ W,
                                                     half* __restrict__ Wt,
                                                     int K, int N) {
    __shared__ float tile[64][33];
    const size_t lsz = (size_t)K * N;
    const float* Wl = W + blockIdx.z * lsz;
    half* Wtl = Wt + blockIdx.z * lsz;
    const int n0 = blockIdx.x * 32, k0 = blockIdx.y * 64;
    const int t = threadIdx.x;
    {
        int col = t & 31, r = t >> 5;
#pragma unroll
        for (int i = 0; i < 8; i++)
            tile[r + i * 8][col] = Wl[(size_t)(k0 + r + i * 8) * N + n0 + col];
    }
    __syncthreads();
    {
        int nrow = t >> 3, kc = (t & 7) * 8;
        half2 hv[4];
#pragma unroll
        for (int j = 0; j < 4; j++)
            hv[j] = __floats2half2_rn(tile[kc + 2 * j][nrow], tile[kc + 2 * j + 1][nrow]);
        *(uint4*)&Wtl[(size_t)(n0 + nrow) * K + k0 + kc] = *(uint4*)hv;
    }
}

// ---------------- emb hi/lo split ----------------
__global__ __launch_bounds__(256) void esplit_kernel(const float* __restrict__ src,
                                                     half* __restrict__ hi,
                                                     half* __restrict__ lo) {
    int idx = blockIdx.x * 256 + threadIdx.x;
    float4 v = ((const float4*)src)[idx];
    half h0 = __float2half_rn(v.x), h1 = __float2half_rn(v.y);
    half h2 = __float2half_rn(v.z), h3 = __float2half_rn(v.w);
    half2 hh0; hh0.x = h0; hh0.y = h1;
    half2 hh1; hh1.x = h2; hh1.y = h3;
    *(half2*)(hi + idx * 4) = hh0; *(half2*)(hi + idx * 4 + 2) = hh1;
    *(half2*)(lo + idx * 4) =
        __floats2half2_rn(v.x - __half2float(h0), v.y - __half2float(h1));
    *(half2*)(lo + idx * 4 + 2) =
        __floats2half2_rn(v.z - __half2float(h2), v.w - __half2float(h3));
}

// ---------------- embedding ----------------
__global__ __launch_bounds__(256) void embed_kernel(const int* __restrict__ ids,
                                                    const float* __restrict__ emb,
                                                    float* __restrict__ out) {
    int m = blockIdx.x, t = threadIdx.x;
    int id = ids[m];
    ((float4*)(out + (size_t)m * Hx))[t] = ((const float4*)(emb + (size_t)id * Hx))[t];
}

// ---------------- layernorm: warp-per-row; MODE 1=half, 2=hi/lo halves ------
template<int MODE>
__global__ __launch_bounds__(256) void ln_kernel(const float* __restrict__ x,
                                                 const float* __restrict__ g,
                                                 const float* __restrict__ b,
                                                 half* __restrict__ outh,
                                                 half* __restrict__ outl) {
    const int lane = threadIdx.x & 31;
    const int m = blockIdx.x * 8 + (threadIdx.x >> 5);
    const float4* xr = (const float4*)(x + (size_t)m * Hx);

    float4 v[8];
    float s = 0.f;
#pragma unroll
    for (int i = 0; i < 8; i++) {
        v[i] = xr[lane + i * 32];
        s += v[i].x + v[i].y + v[i].z + v[i].w;
    }
#pragma unroll
    for (int o = 16; o; o >>= 1) s += __shfl_xor_sync(0xffffffffu, s, o);
    float mu = s * (1.0f / Hx);

    float s2 = 0.f;
#pragma unroll
    for (int i = 0; i < 8; i++) {
        float d0 = v[i].x - mu, d1 = v[i].y - mu, d2 = v[i].z - mu, d3 = v[i].w - mu;
        s2 += d0*d0 + d1*d1 + d2*d2 + d3*d3;
    }
#pragma unroll
    for (int o = 16; o; o >>= 1) s2 += __shfl_xor_sync(0xffffffffu, s2, o);
    float inv = rsqrtf(s2 * (1.0f / Hx) + 1e-5f);

#pragma unroll
    for (int i = 0; i < 8; i++) {
        float4 gg = ((const float4*)g)[lane + i * 32];
        float4 bb = ((const float4*)b)[lane + i * 32];
        float o0 = (v[i].x - mu) * inv * gg.x + bb.x;
        float o1 = (v[i].y - mu) * inv * gg.y + bb.y;
        float o2 = (v[i].z - mu) * inv * gg.z + bb.z;
        float o3 = (v[i].w - mu) * inv * gg.w + bb.w;
        int c = (lane + i * 32) * 4;
        if (MODE == 1) {
            *(half2*)(outh + (size_t)m * Hx + c) = __floats2half2_rn(o0, o1);
            *(half2*)(outh + (size_t)m * Hx + c + 2) = __floats2half2_rn(o2, o3);
        } else {
            half h0 = __float2half_rn(o0), h1 = __float2half_rn(o1);
            half h2 = __float2half_rn(o2), h3 = __float2half_rn(o3);
            half2 hh0; hh0.x = h0; hh0.y = h1;
            half2 hh1; hh1.x = h2; hh1.y = h3;
            *(half2*)(outh + (size_t)m * Hx + c) = hh0;
            *(half2*)(outh + (size_t)m * Hx + c + 2) = hh1;
            *(half2*)(outl + (size_t)m * Hx + c) =
                __floats2half2_rn(o0 - __half2float(h0), o1 - __half2float(h1));
            *(half2*)(outl + (size_t)m * Hx + c + 2) =
                __floats2half2_rn(o2 - __half2float(h2), o3 - __half2float(h3));
        }
    }
}

// ======= fp16 GEMM, 4-stage cp.async + ldmatrix =============================
#define HST 40
#define NSTAGE 4
#define STG_HALVES (128 * HST)
#define GEMM_SMEM (NSTAGE * 2 * STG_HALVES * 2)

template<bool GELU, bool RESID, bool OUT_HALF>
__global__ __launch_bounds__(256, 2) void gemm_h16(const half* __restrict__ A,
                                                   const half* __restrict__ Bw,
                                                   const float* __restrict__ bias,
                                                   const float* __restrict__ R,
                                                   float* __restrict__ C,
                                                   half* __restrict__ Ch,
                                                   int M, int N, int K) {
    extern __shared__ half smh[];
    const int t = threadIdx.x;
    const int warp = t >> 5, lane = t & 31;
    const int g = lane >> 2, q = lane & 3;
    const int wm = warp >> 1, wn = warp & 1;
    const int m0 = blockIdx.y * 128, n0 = blockIdx.x * 128;

    const int f_row = t >> 1, f_ch = (t & 1) * 16;
    const uint32_t smbase = (uint32_t)__cvta_generic_to_shared(smh);

    const int a_off = (wm * 32 + (lane & 15)) * HST + (lane >> 4) * 8;
    const int b_off = (wn * 64 + ((lane >> 4) * 8) + (lane & 7)) * HST + ((lane >> 3) & 1) * 8;

    float acc[2][8][4];
#pragma unroll
    for (int mt = 0; mt < 2; mt++)
#pragma unroll
        for (int nt = 0; nt < 8; nt++)
#pragma unroll
            for (int r = 0; r < 4; r++) acc[mt][nt][r] = 0.f;

    const half* Arow = A + (size_t)(m0 + f_row) * K + f_ch;
    const half* Brow = Bw + (size_t)(n0 + f_row) * K + f_ch;

#pragma unroll
    for (int s = 0; s < NSTAGE - 1; s++) {
        half* as = smh + s * 2 * STG_HALVES;
        half* bs = as + STG_HALVES;
        cp_async16(&as[f_row * HST + f_ch],     Arow + s * 32);
        cp_async16(&as[f_row * HST + f_ch + 8], Arow + s * 32 + 8);
        cp_async16(&bs[f_row * HST + f_ch],     Brow + s * 32);
        cp_async16(&bs[f_row * HST + f_ch + 8], Brow + s * 32 + 8);
        cp_commit();
    }

    const int T = K >> 5;
    for (int i = 0; i < T; i++) {
        const int s = i & (NSTAGE - 1);
        cp_wait2();
        __syncthreads();

        if (i + NSTAGE - 1 < T) {
            const int sn = (i + NSTAGE - 1) & (NSTAGE - 1);
            const int kn = (i + NSTAGE - 1) * 32;
            half* as = smh + sn * 2 * STG_HALVES;
            half* bs = as + STG_HALVES;
            cp_async16(&as[f_row * HST + f_ch],     Arow + kn);
            cp_async16(&as[f_row * HST + f_ch + 8], Arow + kn + 8);
            cp_async16(&bs[f_row * HST + f_ch],     Brow + kn);
            cp_async16(&bs[f_row * HST + f_ch + 8], Brow + kn + 8);
        }
        cp_commit();

        const uint32_t as_b = smbase + (uint32_t)(s * 2 * STG_HALVES) * 2;
        const uint32_t bs_b = as_b + (uint32_t)STG_HALVES * 2;
#pragma unroll
        for (int ks = 0; ks < 2; ks++) {
            const int k = ks * 16;
            uint32_t af[2][4], bf[8][2];
#pragma unroll
            for (int mt = 0; mt < 2; mt++)
                ldsm_x4(af[mt][0], af[mt][1], af[mt][2], af[mt][3],
                        as_b + (uint32_t)(a_off + mt * 16 * HST + k) * 2);
#pragma unroll
            for (int p = 0; p < 4; p++)
                ldsm_x4(bf[2*p][0], bf[2*p][1], bf[2*p+1][0], bf[2*p+1][1],
                        bs_b + (uint32_t)(b_off + p * 16 * HST + k) * 2);
#pragma unroll
            for (int mt = 0; mt < 2; mt++)
#pragma unroll
                for (int nt = 0; nt < 8; nt++)
                    mma_f16(acc[mt][nt], af[mt], bf[nt]);
        }
    }

#pragma unroll
    for (int mt = 0; mt < 2; mt++) {
#pragma unroll
        for (int nt = 0; nt < 8; nt++) {
            int r0 = m0 + wm * 32 + mt * 16 + g;
            int c0 = n0 + wn * 64 + nt * 8 + q * 2;
            float b0 = bias ? bias[c0] : 0.f;
            float b1 = bias ? bias[c0 + 1] : 0.f;
#pragma unroll
            for (int hf = 0; hf < 2; hf++) {
                int row = r0 + hf * 8;
                float v0 = acc[mt][nt][hf * 2 + 0] + b0;
                float v1 = acc[mt][nt][hf * 2 + 1] + b1;
                if (GELU) { v0 = gelu_f(v0); v1 = gelu_f(v1); }
                if (RESID) {
                    const float2 rr = *(const float2*)(R + (size_t)row * N + c0);
                    v0 += rr.x; v1 += rr.y;
                }
                if (OUT_HALF) {
                    *(half2*)(Ch + (size_t)row * N + c0) = __floats2half2_rn(v0, v1);
                } else {
                    float2 o2; o2.x = v0; o2.y = v1;
                    *(float2*)(C + (size_t)row * N + c0) = o2;
                }
            }
        }
    }
}

// ---------------- fused flash attention: fp16 HMMA + masked-tile skip -------
#define AHS 72
#define ATTN_SMEM_BYTES (4 * 64 * AHS * 2)

__global__ __launch_bounds__(128) void attn_kernel(const half* __restrict__ qkv,
                                                   const int* __restrict__ sp,
                                                   half* __restrict__ attn) {
    extern __shared__ half smah[];
    half* Qs = smah;
    half* Ks = Qs + 64 * AHS;
    half* Vs = Ks + 64 * AHS;
    half* Ps = Vs + 64 * AHS;
    const uint32_t qs_b = (uint32_t)__cvta_generic_to_shared(Qs);
    const uint32_t ks_b = (uint32_t)__cvta_generic_to_shared(Ks);
    const uint32_t vs_b = (uint32_t)__cvta_generic_to_shared(Vs);
    const uint32_t ps_b = (uint32_t)__cvta_generic_to_shared(Ps);

    const int it = blockIdx.x, bn = blockIdx.y;
    const int b = bn >> 4, n = bn & 15;
    const int t = threadIdx.x, w = t >> 5, lane = t & 31;
    const int g = lane >> 2, q = lane & 3;
    const int i0 = it * 64;
    const int spv = sp[b];
    const float slope2 = exp2f(-0.5f * (float)(n + 1)) * LOG2E;
    const float qs2 = 0.125f * LOG2E;

#pragma unroll
    for (int l = 0; l < 4; l++) {
        int e = t + l * 128;
        int row = e >> 3, c8 = (e & 7) * 8;
        cp_async16(&Qs[row * AHS + c8],
                   qkv + (size_t)(b * Sx + i0 + row) * 3072 + n * 64 + c8);
    }
    cp_commit();
    cp_wait0();
    __syncthreads();

    const int r0 = w * 16 + g;
    const int a_off = (w * 16 + (lane & 15)) * AHS + (lane >> 4) * 8;
    uint32_t qf[4][4];
#pragma unroll
    for (int kk = 0; kk < 4; kk++)
        ldsm_x4(qf[kk][0], qf[kk][1], qf[kk][2], qf[kk][3],
                qs_b + (uint32_t)(a_off + kk * 16) * 2);

    const int bk_off = (((lane >> 4) * 8) + (lane & 7)) * AHS + ((lane >> 3) & 1) * 8;
    const int vt_off = (((lane >> 3) & 1) * 8 + (lane & 7)) * AHS + (lane >> 4) * 8;

    float o[8][4];
#pragma unroll
    for (int nt = 0; nt < 8; nt++)
#pragma unroll
        for (int c = 0; c < 4; c++) o[nt][c] = 0.f;
    float m0 = -1e30f, m1 = -1e30f, l0 = 0.f, l1 = 0.f;

    const int rowA = i0 + r0, rowB = rowA + 8;

    for (int jt = 0; jt <= it; jt++) {
        const int j0 = jt * 64;
        // fully-masked tile skip (CTA-uniform; contributes exactly zero)
        if (i0 >= spv && j0 + 64 <= spv) continue;

        __syncthreads();
#pragma unroll
        for (int l = 0; l < 4; l++) {
            int e = t + l * 128;
            int row = e >> 3, c8 = (e & 7) * 8;
            const half* base = qkv + (size_t)(b * Sx + j0 + row) * 3072 + n * 64 + c8;
            cp_async16(&Ks[row * AHS + c8], base + 1024);
            cp_async16(&Vs[row * AHS + c8], base + 2048);
        }
        cp_commit();
        cp_wait0();
        __syncthreads();

        float s[8][4];
#pragma unroll
        for (int nt = 0; nt < 8; nt++)
#pragma unroll
            for (int c = 0; c < 4; c++) s[nt][c] = 0.f;
#pragma unroll
        for (int kk = 0; kk < 4; kk++) {
            uint32_t bf[8][2];
#pragma unroll
            for (int p = 0; p < 4; p++)
                ldsm_x4(bf[2*p][0], bf[2*p][1], bf[2*p+1][0], bf[2*p+1][1],
                        ks_b + (uint32_t)(bk_off + p * 16 * AHS + kk * 16) * 2);
#pragma unroll
            for (int nt = 0; nt < 8; nt++)
                mma_f16(s[nt], qf[kk], bf[nt]);
        }

#pragma unroll
        for (int nt = 0; nt < 8; nt++) {
#pragma unroll
            for (int c = 0; c < 4; c++) {
                int i = (c < 2) ? rowA : rowB;
                int j = j0 + nt * 8 + 2 * q + (c & 1);
                bool allowed = (j <= i) && !((i >= spv) && (j < spv));
                s[nt][c] = allowed ? fmaf(s[nt][c], qs2, -slope2 * (float)(i - j)) : -1e30f;
            }
        }

        float mx0 = -1e30f, mx1 = -1e30f;
#pragma unroll
        for (int nt = 0; nt < 8; nt++) {
            mx0 = fmaxf(mx0, fmaxf(s[nt][0], s[nt][1]));
            mx1 = fmaxf(mx1, fmaxf(s[nt][2], s[nt][3]));
        }
        mx0 = fmaxf(mx0, __shfl_xor_sync(0xffffffffu, mx0, 1));
        mx0 = fmaxf(mx0, __shfl_xor_sync(0xffffffffu, mx0, 2));
        mx1 = fmaxf(mx1, __shfl_xor_sync(0xffffffffu, mx1, 1));
        mx1 = fmaxf(mx1, __shfl_xor_sync(0xffffffffu, mx1, 2));
        float mn0 = fmaxf(m0, mx0), mn1 = fmaxf(m1, mx1);
        float al0 = ex2(m0 - mn0), al1 = ex2(m1 - mn1);

        float sum0 = 0.f, sum1 = 0.f;
#pragma unroll
        for (int nt = 0; nt < 8; nt++) {
            float p0 = ex2(s[nt][0] - mn0);
            float p1 = ex2(s[nt][1] - mn0);
            float p2 = ex2(s[nt][2] - mn1);
            float p3 = ex2(s[nt][3] - mn1);
            sum0 += p0 + p1; sum1 += p2 + p3;
            *(half2*)&Ps[(r0    ) * AHS + nt * 8 + 2 * q] = __floats2half2_rn(p0, p1);
            *(half2*)&Ps[(r0 + 8) * AHS + nt * 8 + 2 * q] = __floats2half2_rn(p2, p3);
        }
        sum0 += __shfl_xor_sync(0xffffffffu, sum0, 1);
        sum0 += __shfl_xor_sync(0xffffffffu, sum0, 2);
        sum1 += __shfl_xor_sync(0xffffffffu, sum1, 1);
        sum1 += __shfl_xor_sync(0xffffffffu, sum1, 2);
        l0 = l0 * al0 + sum0;
        l1 = l1 * al1 + sum1;
        m0 = mn0; m1 = mn1;
#pragma unroll
        for (int nt = 0; nt < 8; nt++) {
            o[nt][0] *= al0; o[nt][1] *= al0;
            o[nt][2] *= al1; o[nt][3] *= al1;
        }
        __syncwarp();

#pragma unroll
        for (int kk = 0; kk < 4; kk++) {
            uint32_t pf[4];
            ldsm_x4(pf[0], pf[1], pf[2], pf[3],
                    ps_b + (uint32_t)(a_off + kk * 16) * 2);
            uint32_t bf[8][2];
#pragma unroll
            for (int p = 0; p < 4; p++)
                ldsm_x4_t(bf[2*p][0], bf[2*p][1], bf[2*p+1][0], bf[2*p+1][1],
                          vs_b + (uint32_t)(vt_off + kk * 16 * AHS + p * 16) * 2);
#pragma unroll
            for (int nt = 0; nt < 8; nt++)
                mma_f16(o[nt], pf, bf[nt]);
        }
    }

    const float inv0 = 1.0f / l0, inv1 = 1.0f / l1;
#pragma unroll
    for (int nt = 0; nt < 8; nt++) {
        *(half2*)(attn + (size_t)(b * Sx + rowA) * Hx + n * 64 + nt * 8 + 2 * q) =
            __floats2half2_rn(o[nt][0] * inv0, o[nt][1] * inv0);
        *(half2*)(attn + (size_t)(b * Sx + rowB) * Hx + n * 64 + nt * 8 + 2 * q) =
            __floats2half2_rn(o[nt][2] * inv1, o[nt][3] * inv1);
    }
}

// ---------------- logits: fp16 hi/lo 3-term GEMM, 2-stage ------------------
#define L3_STG (128 * HST)
#define L3_STAGE (4 * L3_STG)
#define L3_SMEM (2 * L3_STAGE * 2)

__global__ __launch_bounds__(256) void gemm_logits3(const half* __restrict__ Ahi,
                                                    const half* __restrict__ Alo,
                                                    const half* __restrict__ Bhi,
                                                    const half* __restrict__ Blo,
                                                    float* __restrict__ C,
                                                    int M, int N, int K) {
    extern __shared__ half smh[];
    const int t = threadIdx.x;
    const int warp = t >> 5, lane = t & 31;
    const int g = lane >> 2, q = lane & 3;
    const int wm = warp >> 1, wn = warp & 1;
    const int m0 = blockIdx.y * 128, n0 = blockIdx.x * 128;

    const int f_row = t >> 1, f_ch = (t & 1) * 16;
    const uint32_t smbase = (uint32_t)__cvta_generic_to_shared(smh);

    const int a_off = (wm * 32 + (lane & 15)) * HST + (lane >> 4) * 8;
    const int b_off = (wn * 64 + ((lane >> 4) * 8) + (lane & 7)) * HST + ((lane >> 3) & 1) * 8;

    float acc[2][8][4];
#pragma unroll
    for (int mt = 0; mt < 2; mt++)
#pragma unroll
        for (int nt = 0; nt < 8; nt++)
#pragma unroll
            for (int r = 0; r < 4; r++) acc[mt][nt][r] = 0.f;

    const half* ArH = Ahi + (size_t)(m0 + f_row) * K + f_ch;
    const half* ArL = Alo + (size_t)(m0 + f_row) * K + f_ch;
    const half* BrH = Bhi + (size_t)(n0 + f_row) * K + f_ch;
    const half* BrL = Blo + (size_t)(n0 + f_row) * K + f_ch;
    const int so = f_row * HST + f_ch;

    {
        half* st = smh;
        cp_async16(&st[so], ArH);                     cp_async16(&st[so + 8], ArH + 8);
        cp_async16(&st[L3_STG + so], ArL);            cp_async16(&st[L3_STG + so + 8], ArL + 8);
        cp_async16(&st[2 * L3_STG + so], BrH);        cp_async16(&st[2 * L3_STG + so + 8], BrH + 8);
        cp_async16(&st[3 * L3_STG + so], BrL);        cp_async16(&st[3 * L3_STG + so + 8], BrL + 8);
        cp_commit();
    }

    const int T = K >> 5;
    for (int i = 0; i < T; i++) {
        cp_wait0();
        __syncthreads();

        if (i + 1 < T) {
            const int kn = (i + 1) * 32;
            half* st = smh + ((i + 1) & 1) * L3_STAGE;
            cp_async16(&st[so], ArH + kn);                cp_async16(&st[so + 8], ArH + kn + 8);
            cp_async16(&st[L3_STG + so], ArL + kn);       cp_async16(&st[L3_STG + so + 8], ArL + kn + 8);
            cp_async16(&st[2 * L3_STG + so], BrH + kn);   cp_async16(&st[2 * L3_STG + so + 8], BrH + kn + 8);
            cp_async16(&st[3 * L3_STG + so], BrL + kn);   cp_async16(&st[3 * L3_STG + so + 8], BrL + kn + 8);
        }
        cp_commit();

        const uint32_t st_b  = smbase + (uint32_t)((i & 1) * L3_STAGE) * 2;
        const uint32_t ah_b = st_b;
        const uint32_t al_b = st_b + (uint32_t)L3_STG * 2;
        const uint32_t bh_b = st_b + (uint32_t)(2 * L3_STG) * 2;
        const uint32_t bl_b = st_b + (uint32_t)(3 * L3_STG) * 2;
#pragma unroll
        for (int ks = 0; ks < 2; ks++) {
            const int k = ks * 16;
            uint32_t ah[2][4], al[2][4], bh[8][2], bl[8][2];
#pragma unroll
            for (int mt = 0; mt < 2; mt++) {
                ldsm_x4(ah[mt][0], ah[mt][1], ah[mt][2], ah[mt][3],
                        ah_b + (uint32_t)(a_off + mt * 16 * HST + k) * 2);
                ldsm_x4(al[mt][0], al[mt][1], al[mt][2], al[mt][3],
                        al_b + (uint32_t)(a_off + mt * 16 * HST + k) * 2);
            }
#pragma unroll
            for (int p = 0; p < 4; p++) {
                ldsm_x4(bh[2*p][0], bh[2*p][1], bh[2*p+1][0], bh[2*p+1][1],
                        bh_b + (uint32_t)(b_off + p * 16 * HST + k) * 2);
                ldsm_x4(bl[2*p][0], bl[2*p][1], bl[2*p+1][0], bl[2*p+1][1],
                        bl_b + (uint32_t)(b_off + p * 16 * HST + k) * 2);
            }
#pragma unroll
            for (int mt = 0; mt < 2; mt++)
#pragma unroll
                for (int nt = 0; nt < 8; nt++) {
                    mma_f16(acc[mt][nt], ah[mt], bl[nt]);
                    mma_f16(acc[mt][nt], al[mt], bh[nt]);
                    mma_f16(acc[mt][nt], ah[mt], bh[nt]);
                }
        }
    }

#pragma unroll
    for (int mt = 0; mt < 2; mt++) {
#pragma unroll
        for (int nt = 0; nt < 8; nt++) {
            int r0 = m0 + wm * 32 + mt * 16 + g;
            int c0 = n0 + wn * 64 + nt * 8 + q * 2;
#pragma unroll
            for (int hf = 0; hf < 2; hf++) {
                int row = r0 + hf * 8;
                float2 o2;
                o2.x = acc[mt][nt][hf * 2 + 0];
                o2.y = acc[mt][nt][hf * 2 + 1];
                *(float2*)(C + (size_t)row * N + c0) = o2;
            }
        }
    }
}

// ---------------- launcher ----------------
extern "C" void kernel_launch(void* const* d_in, const int* in_sizes, int n_in,
                              void* d_out, int out_size) {
    const int*   ids    = (const int*)d_in[0];
    const int*   sp     = (const int*)d_in[1];
    const float* emb    = (const float*)d_in[2];
    const float* ln1_g  = (const float*)d_in[3];
    const float* ln1_b  = (const float*)d_in[4];
    const float* Wqkv   = (const float*)d_in[5];
    const float* bqkv   = (const float*)d_in[6];
    const float* Wo     = (const float*)d_in[7];
    const float* bo     = (const float*)d_in[8];
    const float* ln2_g  = (const float*)d_in[9];
    const float* ln2_b  = (const float*)d_in[10];
    const float* Wfc    = (const float*)d_in[11];
    const float* bfc    = (const float*)d_in[12];
    const float* Wproj  = (const float*)d_in[13];
    const float* bproj  = (const float*)d_in[14];
    const float* lnf_g  = (const float*)d_in[15];
    const float* lnf_b  = (const float*)d_in[16];
    float* out = (float*)d_out;

    float* x;
    half *qkv_h, *hh, *attn_h, *mid_h, *hhi, *hlo, *ehi, *elo;
    half *wqkv_t, *wo_t, *wfc_t, *wproj_t;
    cudaGetSymbolAddress((void**)&x,       g_x);
    cudaGetSymbolAddress((void**)&qkv_h,   g_qkv_h);
    cudaGetSymbolAddress((void**)&hh,      g_hh);
    cudaGetSymbolAddress((void**)&attn_h,  g_attn_h);
    cudaGetSymbolAddress((void**)&mid_h,   g_mid_h);
    cudaGetSymbolAddress((void**)&hhi,     g_hhi);
    cudaGetSymbolAddress((void**)&hlo,     g_hlo);
    cudaGetSymbolAddress((void**)&ehi,     g_ehi);
    cudaGetSymbolAddress((void**)&elo,     g_elo);
    cudaGetSymbolAddress((void**)&wqkv_t,  g_Wqkv_t);
    cudaGetSymbolAddress((void**)&wo_t,    g_Wo_t);
    cudaGetSymbolAddress((void**)&wfc_t,   g_Wfc_t);
    cudaGetSymbolAddress((void**)&wproj_t, g_Wproj_t);

    cudaFuncSetAttribute(attn_kernel, cudaFuncAttributeMaxDynamicSharedMemorySize, ATTN_SMEM_BYTES);
    cudaFuncSetAttribute(gemm_h16<false, false, true>,  cudaFuncAttributeMaxDynamicSharedMemorySize, GEMM_SMEM);
    cudaFuncSetAttribute(gemm_h16<false, true, false>,  cudaFuncAttributeMaxDynamicSharedMemorySize, GEMM_SMEM);
    cudaFuncSetAttribute(gemm_h16<true, false, true>,   cudaFuncAttributeMaxDynamicSharedMemorySize, GEMM_SMEM);
    cudaFuncSetAttribute(gemm_logits3, cudaFuncAttributeMaxDynamicSharedMemorySize, L3_SMEM);

    wtrans_kernel<<<dim3(3 * Hx / 32, Hx / 64, NLx), 256>>>(Wqkv, wqkv_t, Hx, 3 * Hx);
    wtrans_kernel<<<dim3(Hx / 32, Hx / 64, NLx), 256>>>(Wo, wo_t, Hx, Hx);
    wtrans_kernel<<<dim3(Fx / 32, Hx / 64, NLx), 256>>>(Wfc, wfc_t, Hx, Fx);
    wtrans_kernel<<<dim3(Hx / 32, Fx / 64, NLx), 256>>>(Wproj, wproj_t, Fx, Hx);
    esplit_kernel<<<(Vx * Hx / 4) / 256, 256>>>(emb, ehi, elo);

    embed_kernel<<<Mx, 256>>>(ids, emb, x);

    for (int l = 0; l < NLx; l++) {
        ln_kernel<1><<<Mx / 8, 256>>>(x, ln1_g + l * Hx, ln1_b + l * Hx, hh, nullptr);
        gemm_h16<false, false, true><<<dim3(3 * Hx / 128, Mx / 128), 256, GEMM_SMEM>>>(
            hh, wqkv_t + (size_t)l * 3 * Hx * Hx, bqkv + (size_t)l * 3 * Hx, nullptr,
            nullptr, qkv_h, Mx, 3 * Hx, Hx);
        attn_kernel<<<dim3(Sx / 64, Bx * NHx), 128, ATTN_SMEM_BYTES>>>(qkv_h, sp, attn_h);
        gemm_h16<false, true, false><<<dim3(Hx / 128, Mx / 128), 256, GEMM_SMEM>>>(
            attn_h, wo_t + (size_t)l * Hx * Hx, bo + (size_t)l * Hx, x,
            x, nullptr, Mx, Hx, Hx);
        ln_kernel<1><<<Mx / 8, 256>>>(x, ln2_g + l * Hx, ln2_b + l * Hx, hh, nullptr);
        gemm_h16<true, false, true><<<dim3(Fx / 128, Mx / 128), 256, GEMM_SMEM>>>(
            hh, wfc_t + (size_t)l * Fx * Hx, bfc + (size_t)l * Fx, nullptr,
            nullptr, mid_h, Mx, Fx, Hx);
        gemm_h16<false, true, false><<<dim3(Hx / 128, Mx / 128), 256, GEMM_SMEM>>>(
            mid_h, wproj_t + (size_t)l * Hx * Fx, bproj + (size_t)l * Hx, x,
            x, nullptr, Mx, Hx, Fx);
    }

    ln_kernel<2><<<Mx / 8, 256>>>(x, lnf_g, lnf_b, hhi, hlo);
    gemm_logits3<<<dim3(Vx / 128, Mx / 128), 256, L3_SMEM>>>(
        hhi, hlo, ehi, elo, out, Mx, Vx, Hx);
}